// round 3
// baseline (speedup 1.0000x reference)
#include <cuda_runtime.h>

// ---------------------------------------------------------------------------
// EncoderLayer: B=8, T=256, M=64, F=128, H=8, DV=16, TU=MU=64, DFF=512
// Round 1: correct fp32 SIMT implementation. Tiled 64x64x16 SGEMM reused for
// all dense ops; split-K for the long-K projections; implicit-GEMM conv.
// ---------------------------------------------------------------------------

static constexpr int B_ = 8, T_ = 256, M_ = 64, F_ = 128;
static constexpr int H_ = 8, DV_ = 16, DFF_ = 512;
static constexpr int ROWS = B_ * T_ * M_;   // 131072
static constexpr int BT  = B_ * T_;         // 2048
static constexpr int HTU = 512;             // H*TU = H*MU

// ---- scratch (__device__ globals; no allocation allowed) ----
__device__ float g_xm  [B_ * M_ * T_ * F_];     // [B*M, T*F] transposed x
__device__ float g_qt  [BT * HTU];
__device__ float g_kt  [BT * HTU];
__device__ float g_qm  [B_ * M_ * HTU];
__device__ float g_km  [B_ * M_ * HTU];
__device__ float g_v   [ROWS * F_];             // conv output, [b,t,m, h*16+d]
__device__ float g_at  [B_ * H_ * T_ * T_];     // time attention probs
__device__ float g_am  [B_ * H_ * M_ * M_];     // measure attention probs
__device__ float g_tmp [B_ * H_ * T_ * M_ * DV_]; // [bh, q, m*16+d]
__device__ float g_attn[ROWS * F_];             // after both attentions
__device__ float g_y1  [ROWS * F_];             // x + attn@o_w + o_b
__device__ float g_out1[ROWS * F_];             // LN1
__device__ float g_h   [ROWS * DFF_];           // FFN hidden
__device__ float g_y2  [ROWS * F_];             // out1 + ffn
__device__ float g_part[4 * BT * HTU];          // split-K partials (max 4*2048*512)

// ---------------------------------------------------------------------------
// Shared tile compute: 64x64 tile, 16x16 threads, 4x4 micro-tile.
// ---------------------------------------------------------------------------
__device__ __forceinline__ void tile_fma(const float (&As)[16][68],
                                         const float (&Bs)[16][64],
                                         int r0, int c0, float (&acc)[4][4])
{
#pragma unroll
    for (int kk = 0; kk < 16; kk++) {
        float4 a4 = *reinterpret_cast<const float4*>(&As[kk][r0]);
        float4 b4 = *reinterpret_cast<const float4*>(&Bs[kk][c0]);
        float aa[4] = {a4.x, a4.y, a4.z, a4.w};
        float bb[4] = {b4.x, b4.y, b4.z, b4.w};
#pragma unroll
        for (int i = 0; i < 4; i++)
#pragma unroll
            for (int j = 0; j < 4; j++)
                acc[i][j] += aa[i] * bb[j];
    }
}

// ---------------------------------------------------------------------------
// Generic SGEMM: C[M,N] = A[M,K] @ B[K,N] (+bias)(+resid)(relu)
// flags: bit0 = bias, bit1 = relu, bit2 = residual add
// ---------------------------------------------------------------------------
__global__ void sgemm_k(const float* __restrict__ A, const float* __restrict__ Bm,
                        const float* __restrict__ bias, const float* __restrict__ resid,
                        float* __restrict__ C, int Mr, int N, int K, int flags)
{
    __shared__ __align__(16) float As[16][68];
    __shared__ __align__(16) float Bs[16][64];
    int tid = threadIdx.x;
    int rowBase = blockIdx.y * 64, colBase = blockIdx.x * 64;
    int ar = tid >> 2, ac = (tid & 3) << 2;
    int br = tid >> 4, bc = (tid & 15) << 2;
    float acc[4][4] = {};
    for (int k0 = 0; k0 < K; k0 += 16) {
        float4 av = *reinterpret_cast<const float4*>(&A[(long)(rowBase + ar) * K + k0 + ac]);
        As[ac + 0][ar] = av.x; As[ac + 1][ar] = av.y;
        As[ac + 2][ar] = av.z; As[ac + 3][ar] = av.w;
        *reinterpret_cast<float4*>(&Bs[br][bc]) =
            *reinterpret_cast<const float4*>(&Bm[(long)(k0 + br) * N + colBase + bc]);
        __syncthreads();
        tile_fma(As, Bs, (tid >> 4) << 2, (tid & 15) << 2, acc);
        __syncthreads();
    }
    int r0 = (tid >> 4) << 2, c0 = (tid & 15) << 2;
    float4 bv = make_float4(0.f, 0.f, 0.f, 0.f);
    if (flags & 1) bv = *reinterpret_cast<const float4*>(&bias[colBase + c0]);
#pragma unroll
    for (int i = 0; i < 4; i++) {
        long row = rowBase + r0 + i;
        float4 o;
        o.x = acc[i][0] + bv.x; o.y = acc[i][1] + bv.y;
        o.z = acc[i][2] + bv.z; o.w = acc[i][3] + bv.w;
        if (flags & 4) {
            float4 rv = *reinterpret_cast<const float4*>(&resid[row * N + colBase + c0]);
            o.x += rv.x; o.y += rv.y; o.z += rv.z; o.w += rv.w;
        }
        if (flags & 2) {
            o.x = fmaxf(o.x, 0.f); o.y = fmaxf(o.y, 0.f);
            o.z = fmaxf(o.z, 0.f); o.w = fmaxf(o.w, 0.f);
        }
        *reinterpret_cast<float4*>(&C[row * N + colBase + c0]) = o;
    }
}

// ---------------------------------------------------------------------------
// Split-K SGEMM: writes partials Cp[s][M][N] (no bias/epilogue)
// ---------------------------------------------------------------------------
__global__ void sgemm_splitk(const float* __restrict__ A, const float* __restrict__ Bm,
                             float* __restrict__ Cp, int Mr, int N, int K, int kChunk)
{
    __shared__ __align__(16) float As[16][68];
    __shared__ __align__(16) float Bs[16][64];
    int tid = threadIdx.x;
    int rowBase = blockIdx.y * 64, colBase = blockIdx.x * 64;
    int s = blockIdx.z;
    int kBeg = s * kChunk, kEnd = kBeg + kChunk;
    int ar = tid >> 2, ac = (tid & 3) << 2;
    int br = tid >> 4, bc = (tid & 15) << 2;
    float acc[4][4] = {};
    for (int k0 = kBeg; k0 < kEnd; k0 += 16) {
        float4 av = *reinterpret_cast<const float4*>(&A[(long)(rowBase + ar) * K + k0 + ac]);
        As[ac + 0][ar] = av.x; As[ac + 1][ar] = av.y;
        As[ac + 2][ar] = av.z; As[ac + 3][ar] = av.w;
        *reinterpret_cast<float4*>(&Bs[br][bc]) =
            *reinterpret_cast<const float4*>(&Bm[(long)(k0 + br) * N + colBase + bc]);
        __syncthreads();
        tile_fma(As, Bs, (tid >> 4) << 2, (tid & 15) << 2, acc);
        __syncthreads();
    }
    int r0 = (tid >> 4) << 2, c0 = (tid & 15) << 2;
#pragma unroll
    for (int i = 0; i < 4; i++) {
        long row = rowBase + r0 + i;
        float4 o = make_float4(acc[i][0], acc[i][1], acc[i][2], acc[i][3]);
        *reinterpret_cast<float4*>(&Cp[((long)s * Mr + row) * N + colBase + c0]) = o;
    }
}

__global__ void reduce_bias_k(const float* __restrict__ Cp, const float* __restrict__ bias,
                              float* __restrict__ C, int Mr, int N, int S)
{
    int i4 = blockIdx.x * 256 + threadIdx.x;
    long total = (long)Mr * N / 4;
    if (i4 >= total) return;
    long idx = (long)i4 * 4;
    float4 s = *reinterpret_cast<const float4*>(&bias[idx % N]);
    for (int z = 0; z < S; z++) {
        float4 p = *reinterpret_cast<const float4*>(&Cp[(long)z * Mr * N + idx]);
        s.x += p.x; s.y += p.y; s.z += p.z; s.w += p.w;
    }
    *reinterpret_cast<float4*>(&C[idx]) = s;
}

// ---------------------------------------------------------------------------
// 3x3 SAME conv as implicit GEMM. Block = one (b,t) pair (64 m-rows) x 64 out ch.
// ---------------------------------------------------------------------------
__global__ void conv3_k(const float* __restrict__ x, const float* __restrict__ w,
                        const float* __restrict__ bias, float* __restrict__ v)
{
    __shared__ __align__(16) float As[16][68];
    __shared__ __align__(16) float Bs[16][64];
    int tid = threadIdx.x;
    int bt = blockIdx.y;
    int b = bt >> 8, t = bt & 255;
    int colBase = blockIdx.x * 64;
    int ar = tid >> 2, ac = (tid & 3) << 2;
    int br = tid >> 4, bc = (tid & 15) << 2;
    float acc[4][4] = {};
    for (int tap = 0; tap < 9; tap++) {
        int dt = tap / 3, dm = tap % 3;
        int ts = t + dt - 1;
        int ms = ar + dm - 1;
        bool okA = ((unsigned)ts < 256u) && ((unsigned)ms < 64u);
        for (int kc = 0; kc < 8; kc++) {
            float4 av = make_float4(0.f, 0.f, 0.f, 0.f);
            if (okA) {
                av = *reinterpret_cast<const float4*>(
                    &x[((long)(b * 256 + ts) * 64 + ms) * 128 + kc * 16 + ac]);
            }
            As[ac + 0][ar] = av.x; As[ac + 1][ar] = av.y;
            As[ac + 2][ar] = av.z; As[ac + 3][ar] = av.w;
            *reinterpret_cast<float4*>(&Bs[br][bc]) =
                *reinterpret_cast<const float4*>(
                    &w[((long)tap * 128 + kc * 16 + br) * 128 + colBase + bc]);
            __syncthreads();
            tile_fma(As, Bs, (tid >> 4) << 2, (tid & 15) << 2, acc);
            __syncthreads();
        }
    }
    int r0 = (tid >> 4) << 2, c0 = (tid & 15) << 2;
    float4 bv = *reinterpret_cast<const float4*>(&bias[colBase + c0]);
#pragma unroll
    for (int i = 0; i < 4; i++) {
        float4 o = make_float4(acc[i][0] + bv.x, acc[i][1] + bv.y,
                               acc[i][2] + bv.z, acc[i][3] + bv.w);
        *reinterpret_cast<float4*>(&v[((long)bt * 64 + r0 + i) * 128 + colBase + c0]) = o;
    }
}

// ---------------------------------------------------------------------------
// Time attention scores + softmax: one block per (b,h,q), 256 threads = 256 keys
// ---------------------------------------------------------------------------
__global__ void at_softmax_k(const float* __restrict__ qt, const float* __restrict__ kt,
                             float* __restrict__ at)
{
    __shared__ float qv[64];
    __shared__ float red[256];
    int q = blockIdx.x, bh = blockIdx.y;
    int b = bh >> 3, h = bh & 7;
    int tid = threadIdx.x;
    if (tid < 64) qv[tid] = qt[(long)(b * 256 + q) * 512 + h * 64 + tid];
    __syncthreads();
    const float* kr = kt + (long)(b * 256 + tid) * 512 + h * 64;
    float s = 0.f;
#pragma unroll 8
    for (int u = 0; u < 64; u++) s += qv[u] * kr[u];
    s *= 0.125f;  // 1/sqrt(64)
    red[tid] = s; __syncthreads();
    for (int st = 128; st > 0; st >>= 1) {
        if (tid < st) red[tid] = fmaxf(red[tid], red[tid + st]);
        __syncthreads();
    }
    float mx = red[0]; __syncthreads();
    float e = __expf(s - mx);
    red[tid] = e; __syncthreads();
    for (int st = 128; st > 0; st >>= 1) {
        if (tid < st) red[tid] += red[tid + st];
        __syncthreads();
    }
    at[((long)bh * 256 + q) * 256 + tid] = e / red[0];
}

// Measure attention: one block per (b,h,q), 64 threads = 64 keys
__global__ void am_softmax_k(const float* __restrict__ qm, const float* __restrict__ km,
                             float* __restrict__ am)
{
    __shared__ float qv[64];
    __shared__ float red[64];
    int q = blockIdx.x, bh = blockIdx.y;
    int b = bh >> 3, h = bh & 7;
    int tid = threadIdx.x;
    qv[tid] = qm[(long)(b * 64 + q) * 512 + h * 64 + tid];
    __syncthreads();
    const float* kr = km + (long)(b * 64 + tid) * 512 + h * 64;
    float s = 0.f;
#pragma unroll 8
    for (int u = 0; u < 64; u++) s += qv[u] * kr[u];
    s *= 0.125f;  // 1/sqrt(64)
    red[tid] = s; __syncthreads();
    for (int st = 32; st > 0; st >>= 1) {
        if (tid < st) red[tid] = fmaxf(red[tid], red[tid + st]);
        __syncthreads();
    }
    float mx = red[0]; __syncthreads();
    float e = __expf(s - mx);
    red[tid] = e; __syncthreads();
    for (int st = 32; st > 0; st >>= 1) {
        if (tid < st) red[tid] += red[tid + st];
        __syncthreads();
    }
    am[((long)bh * 64 + q) * 64 + tid] = e / red[0];
}

// ---------------------------------------------------------------------------
// tmp[bh, q, m*16+d] = sum_k at[bh,q,k] * v[b,k,m,h*16+d]
// Per (b,h): [256,256] @ [256,1024]. grid (16, 4, 64)
// ---------------------------------------------------------------------------
__global__ void at_v_k(const float* __restrict__ at, const float* __restrict__ v,
                       float* __restrict__ tmp)
{
    __shared__ __align__(16) float As[16][68];
    __shared__ __align__(16) float Bs[16][64];
    int tid = threadIdx.x;
    int bh = blockIdx.z;
    int b = bh >> 3, h = bh & 7;
    const float* A = at + (long)bh * 65536;
    int rowBase = blockIdx.y * 64, colBase = blockIdx.x * 64;
    int ar = tid >> 2, ac = (tid & 3) << 2;
    int br = tid >> 4, bc = (tid & 15) << 2;
    float acc[4][4] = {};
    for (int k0 = 0; k0 < 256; k0 += 16) {
        float4 av = *reinterpret_cast<const float4*>(&A[(rowBase + ar) * 256 + k0 + ac]);
        As[ac + 0][ar] = av.x; As[ac + 1][ar] = av.y;
        As[ac + 2][ar] = av.z; As[ac + 3][ar] = av.w;
        int k = k0 + br;
        int j = colBase + bc;
        int m = j >> 4, d = j & 15;
        *reinterpret_cast<float4*>(&Bs[br][bc]) =
            *reinterpret_cast<const float4*>(
                &v[((long)(b * 256 + k) * 64 + m) * 128 + h * 16 + d]);
        __syncthreads();
        tile_fma(As, Bs, (tid >> 4) << 2, (tid & 15) << 2, acc);
        __syncthreads();
    }
    int r0 = (tid >> 4) << 2, c0 = (tid & 15) << 2;
#pragma unroll
    for (int i = 0; i < 4; i++) {
        float4 o = make_float4(acc[i][0], acc[i][1], acc[i][2], acc[i][3]);
        *reinterpret_cast<float4*>(
            &tmp[(long)bh * 262144 + (rowBase + r0 + i) * 1024 + colBase + c0]) = o;
    }
}

// ---------------------------------------------------------------------------
// attn[b,q,m,h*16+d] = sum_n am[bh,m,n] * tmp[bh,q,n*16+d]
// Per (b,h): [64,64] @ [64, 4096(=q*16+d)]. grid (64, 1, 64)
// ---------------------------------------------------------------------------
__global__ void am_tmp_k(const float* __restrict__ am, const float* __restrict__ tmp,
                         float* __restrict__ attn)
{
    __shared__ __align__(16) float As[16][68];
    __shared__ __align__(16) float Bs[16][64];
    int tid = threadIdx.x;
    int bh = blockIdx.z;
    int b = bh >> 3, h = bh & 7;
    const float* A = am + (long)bh * 4096;
    int colBase = blockIdx.x * 64;
    int ar = tid >> 2, ac = (tid & 3) << 2;
    int br = tid >> 4, bc = (tid & 15) << 2;
    float acc[4][4] = {};
    for (int k0 = 0; k0 < 64; k0 += 16) {
        float4 av = *reinterpret_cast<const float4*>(&A[ar * 64 + k0 + ac]);
        As[ac + 0][ar] = av.x; As[ac + 1][ar] = av.y;
        As[ac + 2][ar] = av.z; As[ac + 3][ar] = av.w;
        int n = k0 + br;
        int j = colBase + bc;
        int q = j >> 4, d = j & 15;
        *reinterpret_cast<float4*>(&Bs[br][bc]) =
            *reinterpret_cast<const float4*>(
                &tmp[(long)bh * 262144 + q * 1024 + n * 16 + d]);
        __syncthreads();
        tile_fma(As, Bs, (tid >> 4) << 2, (tid & 15) << 2, acc);
        __syncthreads();
    }
    int r0 = (tid >> 4) << 2, c0 = (tid & 15) << 2;
    int j0 = colBase + c0;
    int q = j0 >> 4, d0 = j0 & 15;
#pragma unroll
    for (int i = 0; i < 4; i++) {
        int m = r0 + i;
        float4 o = make_float4(acc[i][0], acc[i][1], acc[i][2], acc[i][3]);
        *reinterpret_cast<float4*>(
            &attn[((long)(b * 256 + q) * 64 + m) * 128 + h * 16 + d0]) = o;
    }
}

// ---------------------------------------------------------------------------
// x -> xm transpose: xm[b*64+m][t*128+f] = x[b,t,m,f]
// ---------------------------------------------------------------------------
__global__ void transpose_k(const float* __restrict__ x, float* __restrict__ xm)
{
    int i = blockIdx.x * 256 + threadIdx.x;   // over 4194304 float4s
    int f4 = i & 31;
    int m = (i >> 5) & 63;
    int t = (i >> 11) & 255;
    int b = i >> 19;
    float4 vv = *reinterpret_cast<const float4*>(
        &x[((long)(b * 256 + t) * 64 + m) * 128 + f4 * 4]);
    *reinterpret_cast<float4*>(
        &xm[(long)(b * 64 + m) * 32768 + t * 128 + f4 * 4]) = vv;
}

// ---------------------------------------------------------------------------
// Row LayerNorm over 128 channels. 4 warps/block, one row per warp.
// ---------------------------------------------------------------------------
__global__ void layernorm_k(const float* __restrict__ y, const float* __restrict__ gg,
                            const float* __restrict__ bb, float* __restrict__ out)
{
    int row = blockIdx.x * 4 + (threadIdx.x >> 5);
    int lane = threadIdx.x & 31;
    long base = (long)row * 128 + lane * 4;
    float4 v = *reinterpret_cast<const float4*>(&y[base]);
    float s = v.x + v.y + v.z + v.w;
#pragma unroll
    for (int o = 16; o > 0; o >>= 1) s += __shfl_xor_sync(0xffffffffu, s, o);
    float mean = s * (1.0f / 128.0f);
    float dx = (v.x - mean) * (v.x - mean) + (v.y - mean) * (v.y - mean) +
               (v.z - mean) * (v.z - mean) + (v.w - mean) * (v.w - mean);
#pragma unroll
    for (int o = 16; o > 0; o >>= 1) dx += __shfl_xor_sync(0xffffffffu, dx, o);
    float rstd = rsqrtf(dx * (1.0f / 128.0f) + 1e-6f);
    float4 g4 = *reinterpret_cast<const float4*>(&gg[lane * 4]);
    float4 b4 = *reinterpret_cast<const float4*>(&bb[lane * 4]);
    float4 o4;
    o4.x = (v.x - mean) * rstd * g4.x + b4.x;
    o4.y = (v.y - mean) * rstd * g4.y + b4.y;
    o4.z = (v.z - mean) * rstd * g4.z + b4.z;
    o4.w = (v.w - mean) * rstd * g4.w + b4.w;
    *reinterpret_cast<float4*>(&out[base]) = o4;
}

// ---------------------------------------------------------------------------
// Launch
// ---------------------------------------------------------------------------
extern "C" void kernel_launch(void* const* d_in, const int* in_sizes, int n_in,
                              void* d_out, int out_size)
{
    const float* x    = (const float*)d_in[0];
    const float* qt_w = (const float*)d_in[1];
    const float* qt_b = (const float*)d_in[2];
    const float* kt_w = (const float*)d_in[3];
    const float* kt_b = (const float*)d_in[4];
    const float* qm_w = (const float*)d_in[5];
    const float* qm_b = (const float*)d_in[6];
    const float* km_w = (const float*)d_in[7];
    const float* km_b = (const float*)d_in[8];
    const float* v_k  = (const float*)d_in[9];
    const float* v_b  = (const float*)d_in[10];
    const float* o_w  = (const float*)d_in[11];
    const float* o_b  = (const float*)d_in[12];
    const float* f1_w = (const float*)d_in[13];
    const float* f1_b = (const float*)d_in[14];
    const float* f2_w = (const float*)d_in[15];
    const float* f2_b = (const float*)d_in[16];
    const float* ln1g = (const float*)d_in[17];
    const float* ln1b = (const float*)d_in[18];
    const float* ln2g = (const float*)d_in[19];
    const float* ln2b = (const float*)d_in[20];
    float* out = (float*)d_out;

    float *xm, *qt, *kt, *qm, *km, *v, *at, *am, *tmp, *attn, *y1, *o1, *hh, *y2, *part;
    cudaGetSymbolAddress((void**)&xm,   g_xm);
    cudaGetSymbolAddress((void**)&qt,   g_qt);
    cudaGetSymbolAddress((void**)&kt,   g_kt);
    cudaGetSymbolAddress((void**)&qm,   g_qm);
    cudaGetSymbolAddress((void**)&km,   g_km);
    cudaGetSymbolAddress((void**)&v,    g_v);
    cudaGetSymbolAddress((void**)&at,   g_at);
    cudaGetSymbolAddress((void**)&am,   g_am);
    cudaGetSymbolAddress((void**)&tmp,  g_tmp);
    cudaGetSymbolAddress((void**)&attn, g_attn);
    cudaGetSymbolAddress((void**)&y1,   g_y1);
    cudaGetSymbolAddress((void**)&o1,   g_out1);
    cudaGetSymbolAddress((void**)&hh,   g_h);
    cudaGetSymbolAddress((void**)&y2,   g_y2);
    cudaGetSymbolAddress((void**)&part, g_part);

    // xm = transpose(x)
    transpose_k<<<16384, 256>>>(x, xm);

    // time projections: [2048, 8192] @ [8192, 512], split-K S=4
    sgemm_splitk<<<dim3(8, 32, 4), 256>>>(x, qt_w, part, 2048, 512, 8192, 2048);
    reduce_bias_k<<<1024, 256>>>(part, qt_b, qt, 2048, 512, 4);
    sgemm_splitk<<<dim3(8, 32, 4), 256>>>(x, kt_w, part, 2048, 512, 8192, 2048);
    reduce_bias_k<<<1024, 256>>>(part, kt_b, kt, 2048, 512, 4);

    // measure projections: [512, 32768] @ [32768, 512], split-K S=16
    sgemm_splitk<<<dim3(8, 8, 16), 256>>>(xm, qm_w, part, 512, 512, 32768, 2048);
    reduce_bias_k<<<256, 256>>>(part, qm_b, qm, 512, 512, 16);
    sgemm_splitk<<<dim3(8, 8, 16), 256>>>(xm, km_w, part, 512, 512, 32768, 2048);
    reduce_bias_k<<<256, 256>>>(part, km_b, km, 512, 512, 16);

    // value conv 3x3 SAME
    conv3_k<<<dim3(2, 2048), 256>>>(x, v_k, v_b, v);

    // attention probabilities
    at_softmax_k<<<dim3(256, 64), 256>>>(qt, kt, at);
    am_softmax_k<<<dim3(64, 64), 64>>>(qm, km, am);

    // apply time attention then measure attention
    at_v_k<<<dim3(16, 4, 64), 256>>>(at, v, tmp);
    am_tmp_k<<<dim3(64, 1, 64), 256>>>(am, tmp, attn);

    // output dense + residual, LN1
    sgemm_k<<<dim3(2, 2048), 256>>>(attn, o_w, o_b, x, y1, ROWS, 128, 128, 1 | 4);
    layernorm_k<<<32768, 128>>>(y1, ln1g, ln1b, o1);

    // FFN
    sgemm_k<<<dim3(8, 2048), 256>>>(o1, f1_w, f1_b, nullptr, hh, ROWS, 512, 128, 1 | 2);
    sgemm_k<<<dim3(2, 2048), 256>>>(hh, f2_w, f2_b, o1, y2, ROWS, 128, 512, 1 | 4);
    layernorm_k<<<32768, 128>>>(y2, ln2g, ln2b, out);
}

// round 5
// speedup vs baseline: 1.0854x; 1.0854x over previous
#include <cuda_runtime.h>

// ---------------------------------------------------------------------------
// EncoderLayer: B=8, T=256, M=64, F=128, H=8, DV=16, TU=MU=64, DFF=512
// Round 4: 128x128-tile double-buffered SGEMM (8x8 microtile) for all big
// dense ops; upgraded conv microtile. Attention-apply/softmax/LN unchanged.
// ---------------------------------------------------------------------------

static constexpr int B_ = 8, T_ = 256, M_ = 64, F_ = 128;
static constexpr int H_ = 8, DV_ = 16, DFF_ = 512;
static constexpr int ROWS = B_ * T_ * M_;   // 131072
static constexpr int BT  = B_ * T_;         // 2048
static constexpr int HTU = 512;             // H*TU = H*MU

// ---- scratch (__device__ globals; no allocation allowed) ----
__device__ float g_xm  [B_ * M_ * T_ * F_];
__device__ float g_qt  [BT * HTU];
__device__ float g_kt  [BT * HTU];
__device__ float g_qm  [B_ * M_ * HTU];
__device__ float g_km  [B_ * M_ * HTU];
__device__ float g_v   [ROWS * F_];
__device__ float g_at  [B_ * H_ * T_ * T_];
__device__ float g_am  [B_ * H_ * M_ * M_];
__device__ float g_tmp [B_ * H_ * T_ * M_ * DV_];
__device__ float g_attn[ROWS * F_];
__device__ float g_y1  [ROWS * F_];
__device__ float g_out1[ROWS * F_];
__device__ float g_h   [ROWS * DFF_];
__device__ float g_y2  [ROWS * F_];
__device__ float g_part[4 * BT * HTU];          // split-K partials

// ===========================================================================
// 128x128x8 double-buffered SGEMM core. 256 threads, 8x8 microtile.
// flags: bit0 = bias, bit1 = relu, bit2 = residual add
// ===========================================================================
__global__ __launch_bounds__(256, 2)
void sgemm128_k(const float* __restrict__ A, const float* __restrict__ Bm,
                const float* __restrict__ bias, const float* __restrict__ resid,
                float* __restrict__ C, int N, int K, int flags)
{
    __shared__ __align__(16) float As[2][8][132];
    __shared__ __align__(16) float Bs[2][8][128];
    int tid = threadIdx.x;
    long rowBase = (long)blockIdx.y * 128;
    int colBase = blockIdx.x * 128;

    int arow = tid >> 1, akq = (tid & 1) * 4;   // A loader: row 0..127, k-quad
    int bk = tid >> 5, bc = (tid & 31) * 4;     // B loader: k 0..7, col-quad

    const float* Aptr = A + (rowBase + arow) * K + akq;
    const float* Bptr = Bm + (long)bk * N + colBase + bc;

    int ty = tid >> 4, tx = tid & 15;           // compute: 16x16 threads
    float acc[8][8] = {};

    // preload tile 0
    {
        float4 a0 = *reinterpret_cast<const float4*>(Aptr);
        float4 b0 = *reinterpret_cast<const float4*>(Bptr);
        As[0][akq + 0][arow] = a0.x; As[0][akq + 1][arow] = a0.y;
        As[0][akq + 2][arow] = a0.z; As[0][akq + 3][arow] = a0.w;
        *reinterpret_cast<float4*>(&Bs[0][bk][bc]) = b0;
    }
    __syncthreads();

    int nk = K >> 3;
    for (int kt = 0; kt < nk; kt++) {
        int cur = kt & 1, nxt = cur ^ 1;
        float4 a4, b4;
        bool has = (kt + 1 < nk);
        if (has) {
            a4 = *reinterpret_cast<const float4*>(Aptr + (kt + 1) * 8);
            b4 = *reinterpret_cast<const float4*>(Bptr + (long)(kt + 1) * 8 * N);
        }
#pragma unroll
        for (int kk = 0; kk < 8; kk++) {
            float ar[8], br[8];
            *reinterpret_cast<float4*>(&ar[0]) =
                *reinterpret_cast<const float4*>(&As[cur][kk][ty * 8]);
            *reinterpret_cast<float4*>(&ar[4]) =
                *reinterpret_cast<const float4*>(&As[cur][kk][ty * 8 + 4]);
            *reinterpret_cast<float4*>(&br[0]) =
                *reinterpret_cast<const float4*>(&Bs[cur][kk][tx * 8]);
            *reinterpret_cast<float4*>(&br[4]) =
                *reinterpret_cast<const float4*>(&Bs[cur][kk][tx * 8 + 4]);
#pragma unroll
            for (int i = 0; i < 8; i++)
#pragma unroll
                for (int j = 0; j < 8; j++)
                    acc[i][j] += ar[i] * br[j];
        }
        if (has) {
            As[nxt][akq + 0][arow] = a4.x; As[nxt][akq + 1][arow] = a4.y;
            As[nxt][akq + 2][arow] = a4.z; As[nxt][akq + 3][arow] = a4.w;
            *reinterpret_cast<float4*>(&Bs[nxt][bk][bc]) = b4;
        }
        __syncthreads();
    }

    long row0 = rowBase + ty * 8;
    int c0 = colBase + tx * 8;
    float4 bv0 = make_float4(0.f, 0.f, 0.f, 0.f), bv1 = bv0;
    if (flags & 1) {
        bv0 = *reinterpret_cast<const float4*>(&bias[c0]);
        bv1 = *reinterpret_cast<const float4*>(&bias[c0 + 4]);
    }
#pragma unroll
    for (int i = 0; i < 8; i++) {
        long r = row0 + i;
        float4 o0 = make_float4(acc[i][0] + bv0.x, acc[i][1] + bv0.y,
                                acc[i][2] + bv0.z, acc[i][3] + bv0.w);
        float4 o1 = make_float4(acc[i][4] + bv1.x, acc[i][5] + bv1.y,
                                acc[i][6] + bv1.z, acc[i][7] + bv1.w);
        if (flags & 4) {
            float4 r0v = *reinterpret_cast<const float4*>(&resid[r * N + c0]);
            float4 r1v = *reinterpret_cast<const float4*>(&resid[r * N + c0 + 4]);
            o0.x += r0v.x; o0.y += r0v.y; o0.z += r0v.z; o0.w += r0v.w;
            o1.x += r1v.x; o1.y += r1v.y; o1.z += r1v.z; o1.w += r1v.w;
        }
        if (flags & 2) {
            o0.x = fmaxf(o0.x, 0.f); o0.y = fmaxf(o0.y, 0.f);
            o0.z = fmaxf(o0.z, 0.f); o0.w = fmaxf(o0.w, 0.f);
            o1.x = fmaxf(o1.x, 0.f); o1.y = fmaxf(o1.y, 0.f);
            o1.z = fmaxf(o1.z, 0.f); o1.w = fmaxf(o1.w, 0.f);
        }
        *reinterpret_cast<float4*>(&C[r * N + c0]) = o0;
        *reinterpret_cast<float4*>(&C[r * N + c0 + 4]) = o1;
    }
}

// Split-K version of the same core: writes partials Cp[s][Mr][N].
__global__ __launch_bounds__(256, 2)
void sgemm128_splitk(const float* __restrict__ A, const float* __restrict__ Bm,
                     float* __restrict__ Cp, int Mr, int N, int K, int kChunk)
{
    __shared__ __align__(16) float As[2][8][132];
    __shared__ __align__(16) float Bs[2][8][128];
    int tid = threadIdx.x;
    long rowBase = (long)blockIdx.y * 128;
    int colBase = blockIdx.x * 128;
    int s = blockIdx.z;
    long kBeg = (long)s * kChunk;

    int arow = tid >> 1, akq = (tid & 1) * 4;
    int bk = tid >> 5, bc = (tid & 31) * 4;
    const float* Aptr = A + (rowBase + arow) * K + kBeg + akq;
    const float* Bptr = Bm + (kBeg + bk) * N + colBase + bc;

    int ty = tid >> 4, tx = tid & 15;
    float acc[8][8] = {};
    {
        float4 a0 = *reinterpret_cast<const float4*>(Aptr);
        float4 b0 = *reinterpret_cast<const float4*>(Bptr);
        As[0][akq + 0][arow] = a0.x; As[0][akq + 1][arow] = a0.y;
        As[0][akq + 2][arow] = a0.z; As[0][akq + 3][arow] = a0.w;
        *reinterpret_cast<float4*>(&Bs[0][bk][bc]) = b0;
    }
    __syncthreads();

    int nk = kChunk >> 3;
    for (int kt = 0; kt < nk; kt++) {
        int cur = kt & 1, nxt = cur ^ 1;
        float4 a4, b4;
        bool has = (kt + 1 < nk);
        if (has) {
            a4 = *reinterpret_cast<const float4*>(Aptr + (kt + 1) * 8);
            b4 = *reinterpret_cast<const float4*>(Bptr + (long)(kt + 1) * 8 * N);
        }
#pragma unroll
        for (int kk = 0; kk < 8; kk++) {
            float ar[8], br[8];
            *reinterpret_cast<float4*>(&ar[0]) =
                *reinterpret_cast<const float4*>(&As[cur][kk][ty * 8]);
            *reinterpret_cast<float4*>(&ar[4]) =
                *reinterpret_cast<const float4*>(&As[cur][kk][ty * 8 + 4]);
            *reinterpret_cast<float4*>(&br[0]) =
                *reinterpret_cast<const float4*>(&Bs[cur][kk][tx * 8]);
            *reinterpret_cast<float4*>(&br[4]) =
                *reinterpret_cast<const float4*>(&Bs[cur][kk][tx * 8 + 4]);
#pragma unroll
            for (int i = 0; i < 8; i++)
#pragma unroll
                for (int j = 0; j < 8; j++)
                    acc[i][j] += ar[i] * br[j];
        }
        if (has) {
            As[nxt][akq + 0][arow] = a4.x; As[nxt][akq + 1][arow] = a4.y;
            As[nxt][akq + 2][arow] = a4.z; As[nxt][akq + 3][arow] = a4.w;
            *reinterpret_cast<float4*>(&Bs[nxt][bk][bc]) = b4;
        }
        __syncthreads();
    }

    long row0 = rowBase + ty * 8;
    int c0 = colBase + tx * 8;
#pragma unroll
    for (int i = 0; i < 8; i++) {
        long r = row0 + i;
        float4 o0 = make_float4(acc[i][0], acc[i][1], acc[i][2], acc[i][3]);
        float4 o1 = make_float4(acc[i][4], acc[i][5], acc[i][6], acc[i][7]);
        *reinterpret_cast<float4*>(&Cp[((long)s * Mr + r) * N + c0]) = o0;
        *reinterpret_cast<float4*>(&Cp[((long)s * Mr + r) * N + c0 + 4]) = o1;
    }
}

__global__ void reduce_bias_k(const float* __restrict__ Cp, const float* __restrict__ bias,
                              float* __restrict__ C, int Mr, int N, int S)
{
    int i4 = blockIdx.x * 256 + threadIdx.x;
    long total = (long)Mr * N / 4;
    if (i4 >= total) return;
    long idx = (long)i4 * 4;
    float4 s = *reinterpret_cast<const float4*>(&bias[idx % N]);
    for (int z = 0; z < S; z++) {
        float4 p = *reinterpret_cast<const float4*>(&Cp[(long)z * Mr * N + idx]);
        s.x += p.x; s.y += p.y; s.z += p.z; s.w += p.w;
    }
    *reinterpret_cast<float4*>(&C[idx]) = s;
}

// ===========================================================================
// 3x3 SAME conv, implicit GEMM. One block per (b,t): 64 m-rows x 128 out ch.
// 256 threads, 8x4 microtile, k-tile 8.
// ===========================================================================
__global__ __launch_bounds__(256, 2)
void conv3_k(const float* __restrict__ x, const float* __restrict__ w,
             const float* __restrict__ bias, float* __restrict__ v)
{
    __shared__ __align__(16) float As[8][68];
    __shared__ __align__(16) float Bs[8][128];
    int tid = threadIdx.x;
    int bt = blockIdx.x;
    int b = bt >> 8, t = bt & 255;

    int ty = tid >> 5, tx = tid & 31;   // rows ty*8, cols tx*4
    float acc[8][4] = {};

    int arow = tid >> 1, akq = (tid & 1) * 4;   // A loader (threads < 128)
    int bk = tid >> 5, bc = (tid & 31) * 4;     // B loader

    for (int tap = 0; tap < 9; tap++) {
        int dt = tap / 3, dm = tap % 3;
        int ts = t + dt - 1;
        int ms = arow + dm - 1;
        bool okA = ((unsigned)ts < 256u) && ((unsigned)ms < 64u) && (tid < 128);
        const float* xrow = x + ((long)(b * 256 + ts) * 64 + ms) * 128;
        for (int kc = 0; kc < 16; kc++) {
            if (tid < 128) {
                float4 av = make_float4(0.f, 0.f, 0.f, 0.f);
                if (okA) av = *reinterpret_cast<const float4*>(&xrow[kc * 8 + akq]);
                As[akq + 0][arow] = av.x; As[akq + 1][arow] = av.y;
                As[akq + 2][arow] = av.z; As[akq + 3][arow] = av.w;
            }
            *reinterpret_cast<float4*>(&Bs[bk][bc]) =
                *reinterpret_cast<const float4*>(
                    &w[((long)tap * 128 + kc * 8 + bk) * 128 + bc]);
            __syncthreads();
#pragma unroll
            for (int kk = 0; kk < 8; kk++) {
                float ar[8], br[4];
                *reinterpret_cast<float4*>(&ar[0]) =
                    *reinterpret_cast<const float4*>(&As[kk][ty * 8]);
                *reinterpret_cast<float4*>(&ar[4]) =
                    *reinterpret_cast<const float4*>(&As[kk][ty * 8 + 4]);
                *reinterpret_cast<float4*>(&br[0]) =
                    *reinterpret_cast<const float4*>(&Bs[kk][tx * 4]);
#pragma unroll
                for (int i = 0; i < 8; i++)
#pragma unroll
                    for (int j = 0; j < 4; j++)
                        acc[i][j] += ar[i] * br[j];
            }
            __syncthreads();
        }
    }

    float4 bv = *reinterpret_cast<const float4*>(&bias[tx * 4]);
#pragma unroll
    for (int i = 0; i < 8; i++) {
        int m = ty * 8 + i;
        float4 o = make_float4(acc[i][0] + bv.x, acc[i][1] + bv.y,
                               acc[i][2] + bv.z, acc[i][3] + bv.w);
        *reinterpret_cast<float4*>(&v[((long)bt * 64 + m) * 128 + tx * 4]) = o;
    }
}

// ===========================================================================
// Attention prob kernels (unchanged from R3)
// ===========================================================================
__global__ void at_softmax_k(const float* __restrict__ qt, const float* __restrict__ kt,
                             float* __restrict__ at)
{
    __shared__ float qv[64];
    __shared__ float red[256];
    int q = blockIdx.x, bh = blockIdx.y;
    int b = bh >> 3, h = bh & 7;
    int tid = threadIdx.x;
    if (tid < 64) qv[tid] = qt[(long)(b * 256 + q) * 512 + h * 64 + tid];
    __syncthreads();
    const float* kr = kt + (long)(b * 256 + tid) * 512 + h * 64;
    float s = 0.f;
#pragma unroll 8
    for (int u = 0; u < 64; u++) s += qv[u] * kr[u];
    s *= 0.125f;
    red[tid] = s; __syncthreads();
    for (int st = 128; st > 0; st >>= 1) {
        if (tid < st) red[tid] = fmaxf(red[tid], red[tid + st]);
        __syncthreads();
    }
    float mx = red[0]; __syncthreads();
    float e = __expf(s - mx);
    red[tid] = e; __syncthreads();
    for (int st = 128; st > 0; st >>= 1) {
        if (tid < st) red[tid] += red[tid + st];
        __syncthreads();
    }
    at[((long)bh * 256 + q) * 256 + tid] = e / red[0];
}

__global__ void am_softmax_k(const float* __restrict__ qm, const float* __restrict__ km,
                             float* __restrict__ am)
{
    __shared__ float qv[64];
    __shared__ float red[64];
    int q = blockIdx.x, bh = blockIdx.y;
    int b = bh >> 3, h = bh & 7;
    int tid = threadIdx.x;
    qv[tid] = qm[(long)(b * 64 + q) * 512 + h * 64 + tid];
    __syncthreads();
    const float* kr = km + (long)(b * 64 + tid) * 512 + h * 64;
    float s = 0.f;
#pragma unroll 8
    for (int u = 0; u < 64; u++) s += qv[u] * kr[u];
    s *= 0.125f;
    red[tid] = s; __syncthreads();
    for (int st = 32; st > 0; st >>= 1) {
        if (tid < st) red[tid] = fmaxf(red[tid], red[tid + st]);
        __syncthreads();
    }
    float mx = red[0]; __syncthreads();
    float e = __expf(s - mx);
    red[tid] = e; __syncthreads();
    for (int st = 32; st > 0; st >>= 1) {
        if (tid < st) red[tid] += red[tid + st];
        __syncthreads();
    }
    am[((long)bh * 64 + q) * 64 + tid] = e / red[0];
}

// ===========================================================================
// Attention apply kernels (unchanged 64x64 core from R3)
// ===========================================================================
__device__ __forceinline__ void tile_fma(const float (&As)[16][68],
                                         const float (&Bs)[16][64],
                                         int r0, int c0, float (&acc)[4][4])
{
#pragma unroll
    for (int kk = 0; kk < 16; kk++) {
        float4 a4 = *reinterpret_cast<const float4*>(&As[kk][r0]);
        float4 b4 = *reinterpret_cast<const float4*>(&Bs[kk][c0]);
        float aa[4] = {a4.x, a4.y, a4.z, a4.w};
        float bb[4] = {b4.x, b4.y, b4.z, b4.w};
#pragma unroll
        for (int i = 0; i < 4; i++)
#pragma unroll
            for (int j = 0; j < 4; j++)
                acc[i][j] += aa[i] * bb[j];
    }
}

__global__ void at_v_k(const float* __restrict__ at, const float* __restrict__ v,
                       float* __restrict__ tmp)
{
    __shared__ __align__(16) float As[16][68];
    __shared__ __align__(16) float Bs[16][64];
    int tid = threadIdx.x;
    int bh = blockIdx.z;
    int b = bh >> 3, h = bh & 7;
    const float* A = at + (long)bh * 65536;
    int rowBase = blockIdx.y * 64, colBase = blockIdx.x * 64;
    int ar = tid >> 2, ac = (tid & 3) << 2;
    int br = tid >> 4, bc = (tid & 15) << 2;
    float acc[4][4] = {};
    for (int k0 = 0; k0 < 256; k0 += 16) {
        float4 av = *reinterpret_cast<const float4*>(&A[(rowBase + ar) * 256 + k0 + ac]);
        As[ac + 0][ar] = av.x; As[ac + 1][ar] = av.y;
        As[ac + 2][ar] = av.z; As[ac + 3][ar] = av.w;
        int k = k0 + br;
        int j = colBase + bc;
        int m = j >> 4, d = j & 15;
        *reinterpret_cast<float4*>(&Bs[br][bc]) =
            *reinterpret_cast<const float4*>(
                &v[((long)(b * 256 + k) * 64 + m) * 128 + h * 16 + d]);
        __syncthreads();
        tile_fma(As, Bs, (tid >> 4) << 2, (tid & 15) << 2, acc);
        __syncthreads();
    }
    int r0 = (tid >> 4) << 2, c0 = (tid & 15) << 2;
#pragma unroll
    for (int i = 0; i < 4; i++) {
        float4 o = make_float4(acc[i][0], acc[i][1], acc[i][2], acc[i][3]);
        *reinterpret_cast<float4*>(
            &tmp[(long)bh * 262144 + (rowBase + r0 + i) * 1024 + colBase + c0]) = o;
    }
}

__global__ void am_tmp_k(const float* __restrict__ am, const float* __restrict__ tmp,
                         float* __restrict__ attn)
{
    __shared__ __align__(16) float As[16][68];
    __shared__ __align__(16) float Bs[16][64];
    int tid = threadIdx.x;
    int bh = blockIdx.z;
    int b = bh >> 3, h = bh & 7;
    const float* A = am + (long)bh * 4096;
    int colBase = blockIdx.x * 64;
    int ar = tid >> 2, ac = (tid & 3) << 2;
    int br = tid >> 4, bc = (tid & 15) << 2;
    float acc[4][4] = {};
    for (int k0 = 0; k0 < 64; k0 += 16) {
        float4 av = *reinterpret_cast<const float4*>(&A[ar * 64 + k0 + ac]);
        As[ac + 0][ar] = av.x; As[ac + 1][ar] = av.y;
        As[ac + 2][ar] = av.z; As[ac + 3][ar] = av.w;
        int n = k0 + br;
        int j = colBase + bc;
        int q = j >> 4, d = j & 15;
        *reinterpret_cast<float4*>(&Bs[br][bc]) =
            *reinterpret_cast<const float4*>(
                &tmp[(long)bh * 262144 + q * 1024 + n * 16 + d]);
        __syncthreads();
        tile_fma(As, Bs, (tid >> 4) << 2, (tid & 15) << 2, acc);
        __syncthreads();
    }
    int r0 = (tid >> 4) << 2, c0 = (tid & 15) << 2;
    int j0 = colBase + c0;
    int q = j0 >> 4, d0 = j0 & 15;
#pragma unroll
    for (int i = 0; i < 4; i++) {
        int m = r0 + i;
        float4 o = make_float4(acc[i][0], acc[i][1], acc[i][2], acc[i][3]);
        *reinterpret_cast<float4*>(
            &attn[((long)(b * 256 + q) * 64 + m) * 128 + h * 16 + d0]) = o;
    }
}

// ===========================================================================
// transpose + layernorm (unchanged)
// ===========================================================================
__global__ void transpose_k(const float* __restrict__ x, float* __restrict__ xm)
{
    int i = blockIdx.x * 256 + threadIdx.x;
    int f4 = i & 31;
    int m = (i >> 5) & 63;
    int t = (i >> 11) & 255;
    int b = i >> 19;
    float4 vv = *reinterpret_cast<const float4*>(
        &x[((long)(b * 256 + t) * 64 + m) * 128 + f4 * 4]);
    *reinterpret_cast<float4*>(
        &xm[(long)(b * 64 + m) * 32768 + t * 128 + f4 * 4]) = vv;
}

__global__ void layernorm_k(const float* __restrict__ y, const float* __restrict__ gg,
                            const float* __restrict__ bb, float* __restrict__ out)
{
    int row = blockIdx.x * 4 + (threadIdx.x >> 5);
    int lane = threadIdx.x & 31;
    long base = (long)row * 128 + lane * 4;
    float4 v = *reinterpret_cast<const float4*>(&y[base]);
    float s = v.x + v.y + v.z + v.w;
#pragma unroll
    for (int o = 16; o > 0; o >>= 1) s += __shfl_xor_sync(0xffffffffu, s, o);
    float mean = s * (1.0f / 128.0f);
    float dx = (v.x - mean) * (v.x - mean) + (v.y - mean) * (v.y - mean) +
               (v.z - mean) * (v.z - mean) + (v.w - mean) * (v.w - mean);
#pragma unroll
    for (int o = 16; o > 0; o >>= 1) dx += __shfl_xor_sync(0xffffffffu, dx, o);
    float rstd = rsqrtf(dx * (1.0f / 128.0f) + 1e-6f);
    float4 g4 = *reinterpret_cast<const float4*>(&gg[lane * 4]);
    float4 b4 = *reinterpret_cast<const float4*>(&bb[lane * 4]);
    float4 o4;
    o4.x = (v.x - mean) * rstd * g4.x + b4.x;
    o4.y = (v.y - mean) * rstd * g4.y + b4.y;
    o4.z = (v.z - mean) * rstd * g4.z + b4.z;
    o4.w = (v.w - mean) * rstd * g4.w + b4.w;
    *reinterpret_cast<float4*>(&out[base]) = o4;
}

// ---------------------------------------------------------------------------
// Launch
// ---------------------------------------------------------------------------
extern "C" void kernel_launch(void* const* d_in, const int* in_sizes, int n_in,
                              void* d_out, int out_size)
{
    const float* x    = (const float*)d_in[0];
    const float* qt_w = (const float*)d_in[1];
    const float* qt_b = (const float*)d_in[2];
    const float* kt_w = (const float*)d_in[3];
    const float* kt_b = (const float*)d_in[4];
    const float* qm_w = (const float*)d_in[5];
    const float* qm_b = (const float*)d_in[6];
    const float* km_w = (const float*)d_in[7];
    const float* km_b = (const float*)d_in[8];
    const float* v_k  = (const float*)d_in[9];
    const float* v_b  = (const float*)d_in[10];
    const float* o_w  = (const float*)d_in[11];
    const float* o_b  = (const float*)d_in[12];
    const float* f1_w = (const float*)d_in[13];
    const float* f1_b = (const float*)d_in[14];
    const float* f2_w = (const float*)d_in[15];
    const float* f2_b = (const float*)d_in[16];
    const float* ln1g = (const float*)d_in[17];
    const float* ln1b = (const float*)d_in[18];
    const float* ln2g = (const float*)d_in[19];
    const float* ln2b = (const float*)d_in[20];
    float* out = (float*)d_out;

    float *xm, *qt, *kt, *qm, *km, *v, *at, *am, *tmp, *attn, *y1, *o1, *hh, *y2, *part;
    cudaGetSymbolAddress((void**)&xm,   g_xm);
    cudaGetSymbolAddress((void**)&qt,   g_qt);
    cudaGetSymbolAddress((void**)&kt,   g_kt);
    cudaGetSymbolAddress((void**)&qm,   g_qm);
    cudaGetSymbolAddress((void**)&km,   g_km);
    cudaGetSymbolAddress((void**)&v,    g_v);
    cudaGetSymbolAddress((void**)&at,   g_at);
    cudaGetSymbolAddress((void**)&am,   g_am);
    cudaGetSymbolAddress((void**)&tmp,  g_tmp);
    cudaGetSymbolAddress((void**)&attn, g_attn);
    cudaGetSymbolAddress((void**)&y1,   g_y1);
    cudaGetSymbolAddress((void**)&o1,   g_out1);
    cudaGetSymbolAddress((void**)&hh,   g_h);
    cudaGetSymbolAddress((void**)&y2,   g_y2);
    cudaGetSymbolAddress((void**)&part, g_part);

    // xm = transpose(x)
    transpose_k<<<16384, 256>>>(x, xm);

    // time projections: [2048, 8192] @ [8192, 512], split-K S=4
    sgemm128_splitk<<<dim3(4, 16, 4), 256>>>(x, qt_w, part, 2048, 512, 8192, 2048);
    reduce_bias_k<<<1024, 256>>>(part, qt_b, qt, 2048, 512, 4);
    sgemm128_splitk<<<dim3(4, 16, 4), 256>>>(x, kt_w, part, 2048, 512, 8192, 2048);
    reduce_bias_k<<<1024, 256>>>(part, kt_b, kt, 2048, 512, 4);

    // measure projections: [512, 32768] @ [32768, 512], split-K S=16
    sgemm128_splitk<<<dim3(4, 4, 16), 256>>>(xm, qm_w, part, 512, 512, 32768, 2048);
    reduce_bias_k<<<256, 256>>>(part, qm_b, qm, 512, 512, 16);
    sgemm128_splitk<<<dim3(4, 4, 16), 256>>>(xm, km_w, part, 512, 512, 32768, 2048);
    reduce_bias_k<<<256, 256>>>(part, km_b, km, 512, 512, 16);

    // value conv 3x3 SAME
    conv3_k<<<2048, 256>>>(x, v_k, v_b, v);

    // attention probabilities
    at_softmax_k<<<dim3(256, 64), 256>>>(qt, kt, at);
    am_softmax_k<<<dim3(64, 64), 64>>>(qm, km, am);

    // apply time attention then measure attention
    at_v_k<<<dim3(16, 4, 64), 256>>>(at, v, tmp);
    am_tmp_k<<<dim3(64, 1, 64), 256>>>(am, tmp, attn);

    // output dense + residual, LN1
    sgemm128_k<<<dim3(1, 1024), 256>>>(attn, o_w, o_b, x, y1, 128, 128, 1 | 4);
    layernorm_k<<<32768, 128>>>(y1, ln1g, ln1b, o1);

    // FFN
    sgemm128_k<<<dim3(4, 1024), 256>>>(o1, f1_w, f1_b, nullptr, hh, 512, 128, 1 | 2);
    sgemm128_k<<<dim3(1, 1024), 256>>>(hh, f2_w, f2_b, o1, y2, 128, 512, 1 | 4);
    layernorm_k<<<32768, 128>>>(y2, ln2g, ln2b, out);
}

// round 10
// speedup vs baseline: 1.5846x; 1.4599x over previous
#include <cuda_runtime.h>
#include <cuda_bf16.h>
#include <cstdint>

// ---------------------------------------------------------------------------
// EncoderLayer: B=8, T=256, M=64, F=128, H=8, DV=16, TU=MU=64, DFF=512
// Round 8: HMMA (mma.sync m16n8k16 bf16, arch-generic) GEMM with bf16 hi/lo
// 3-term split for all big GEMMs. tcgen05 is unavailable (ptxas target sm_103).
// ---------------------------------------------------------------------------

static constexpr int B_ = 8, T_ = 256, M_ = 64, F_ = 128;
static constexpr int H_ = 8, DV_ = 16, DFF_ = 512;
static constexpr int ROWS = B_ * T_ * M_;   // 131072
static constexpr int BT  = B_ * T_;         // 2048
static constexpr int HTU = 512;
static constexpr long KCONV = 1152;         // 9 taps * 128 ch

// ---- fp32 scratch ----
__device__ float g_qt  [BT * HTU];
__device__ float g_kt  [BT * HTU];
__device__ float g_qm  [B_ * M_ * HTU];
__device__ float g_km  [B_ * M_ * HTU];
__device__ float g_v   [ROWS * F_];
__device__ float g_at  [B_ * H_ * T_ * T_];
__device__ float g_am  [B_ * H_ * M_ * M_];
__device__ float g_tmp [(long)B_ * H_ * T_ * M_ * DV_];
__device__ float g_y1  [ROWS * F_];
__device__ float g_out1[ROWS * F_];
__device__ float g_y2  [ROWS * F_];
__device__ float g_part[16 * 512 * 512];    // split-K partials

// ---- bf16 hi/lo operands ----
__device__ __nv_bfloat16 g_xh  [(long)BT * 8192],  g_xl  [(long)BT * 8192];
__device__ __nv_bfloat16 g_xmh [(long)512 * 32768], g_xml [(long)512 * 32768];
__device__ __nv_bfloat16 g_qtwh[(long)512 * 8192],  g_qtwl[(long)512 * 8192];
__device__ __nv_bfloat16 g_ktwh[(long)512 * 8192],  g_ktwl[(long)512 * 8192];
__device__ __nv_bfloat16 g_qmwh[(long)512 * 32768], g_qmwl[(long)512 * 32768];
__device__ __nv_bfloat16 g_kmwh[(long)512 * 32768], g_kmwl[(long)512 * 32768];
__device__ __nv_bfloat16 g_f1wh[512 * 128], g_f1wl[512 * 128];
__device__ __nv_bfloat16 g_f2wh[128 * 512], g_f2wl[128 * 512];
__device__ __nv_bfloat16 g_owh [128 * 128], g_owl [128 * 128];
__device__ __nv_bfloat16 g_vwh [128 * 1152], g_vwl[128 * 1152];
__device__ __nv_bfloat16 g_im2h[(long)ROWS * KCONV], g_im2l[(long)ROWS * KCONV];
__device__ __nv_bfloat16 g_o1h [(long)ROWS * 128],  g_o1l [(long)ROWS * 128];
__device__ __nv_bfloat16 g_hhh [(long)ROWS * 512],  g_hhl [(long)ROWS * 512];
__device__ __nv_bfloat16 g_ath [(long)ROWS * 128],  g_atl [(long)ROWS * 128];

// ===========================================================================
// PTX helpers (all arch-generic: sm_80+ features)
// ===========================================================================
__device__ __forceinline__ uint32_t smem_to_u32(const void* p) {
    uint32_t a;
    asm("{ .reg .u64 t; cvta.to.shared.u64 t, %1; cvt.u32.u64 %0, t; }" : "=r"(a) : "l"(p));
    return a;
}
__device__ __forceinline__ void ldsm_x4(uint32_t* r, uint32_t addr) {
    asm volatile("ldmatrix.sync.aligned.m8n8.x4.shared.b16 {%0,%1,%2,%3}, [%4];"
                 : "=r"(r[0]), "=r"(r[1]), "=r"(r[2]), "=r"(r[3]) : "r"(addr));
}
__device__ __forceinline__ void mma16816(float* d, const uint32_t* a, const uint32_t* b) {
    asm volatile("mma.sync.aligned.m16n8k16.row.col.f32.bf16.bf16.f32 "
                 "{%0,%1,%2,%3}, {%4,%5,%6,%7}, {%8,%9}, {%0,%1,%2,%3};"
                 : "+f"(d[0]), "+f"(d[1]), "+f"(d[2]), "+f"(d[3])
                 : "r"(a[0]), "r"(a[1]), "r"(a[2]), "r"(a[3]), "r"(b[0]), "r"(b[1]));
}
#define CP_ASYNC16(sm, gp) \
    asm volatile("cp.async.cg.shared.global [%0], [%1], 16;" :: "r"(sm), "l"(gp))
#define CP_COMMIT() asm volatile("cp.async.commit_group;" ::: "memory")
#define CP_WAIT0()  asm volatile("cp.async.wait_group 0;" ::: "memory")
#define CP_WAIT1()  asm volatile("cp.async.wait_group 1;" ::: "memory")

// flags
static constexpr int GF_BIAS = 1, GF_RELU = 2, GF_RESID = 4, GF_OUTF = 8,
                     GF_OUTBF = 16, GF_SPLIT = 32;

// SMEM layout: 2 stages x 4 tiles (Ah,Al,Bh,Bl), each 128 rows x 40 bf16 (80B)
static constexpr int TILE_B   = 128 * 80;        // 10240 bytes per tile
static constexpr int STAGE_B  = 4 * TILE_B;      // 40960
static constexpr int MMA_SMEM = 2 * STAGE_B;     // 81920

__device__ __forceinline__ void fsplit(float v, __nv_bfloat16& h, __nv_bfloat16& l) {
    h = __float2bfloat16(v);
    l = __float2bfloat16(v - __bfloat162float(h));
}

// ===========================================================================
// HMMA GEMM: C[Mr,N] = (Ah+Al)[Mr,K] @ (Bh+Bl)[N,K]^T  (3-term hi/lo)
// grid = (N/128, Mr/128, S); block = 256 (8 warps, each 64x32).
// kChunk multiple of 32.
// ===========================================================================
__global__ __launch_bounds__(256, 2)
void mma_gemm(const __nv_bfloat16* __restrict__ Ah, const __nv_bfloat16* __restrict__ Al,
              const __nv_bfloat16* __restrict__ Bh, const __nv_bfloat16* __restrict__ Bl,
              const float* __restrict__ bias, const float* __restrict__ resid,
              float* __restrict__ Cf, __nv_bfloat16* __restrict__ Chi,
              __nv_bfloat16* __restrict__ Clo,
              long Mr, int N, long K, int kChunk, int flags)
{
    extern __shared__ char smem[];
    uint32_t sb = smem_to_u32(smem);
    int tid = threadIdx.x, wid = tid >> 5, lane = tid & 31;
    int warp_m = wid >> 2, warp_n = wid & 3;    // 2 x 4 warps

    long rowBase = (long)blockIdx.y * 128;
    int  colBase = blockIdx.x * 128;
    long kBeg = (long)blockIdx.z * kChunk;

    // ---- loaders: thread covers row=tid>>1, half=tid&1 (16 bf16 = 32B) ----
    int lrow = tid >> 1, lhalf = tid & 1;
    const __nv_bfloat16* gA[2] = { Ah + (rowBase + lrow) * K + kBeg,
                                   Al + (rowBase + lrow) * K + kBeg };
    const __nv_bfloat16* gB[2] = { Bh + (long)(colBase + lrow) * K + kBeg,
                                   Bl + (long)(colBase + lrow) * K + kBeg };
    uint32_t soBase = (uint32_t)(lrow * 80 + lhalf * 32);

    auto prefetch = [&](int kt, int st) {
        long off = (long)kt * 32 + lhalf * 16;
        uint32_t s0 = sb + st * STAGE_B + soBase;
        CP_ASYNC16(s0 + 0 * TILE_B,      gA[0] + off);
        CP_ASYNC16(s0 + 0 * TILE_B + 16, gA[0] + off + 8);
        CP_ASYNC16(s0 + 1 * TILE_B,      gA[1] + off);
        CP_ASYNC16(s0 + 1 * TILE_B + 16, gA[1] + off + 8);
        CP_ASYNC16(s0 + 2 * TILE_B,      gB[0] + off);
        CP_ASYNC16(s0 + 2 * TILE_B + 16, gB[0] + off + 8);
        CP_ASYNC16(s0 + 3 * TILE_B,      gB[1] + off);
        CP_ASYNC16(s0 + 3 * TILE_B + 16, gB[1] + off + 8);
    };

    // ldmatrix lane-address components
    int a_row = warp_m * 64 + (lane & 7) + ((lane >> 3) & 1) * 8;  // + mi*16
    int a_k8  = (lane >> 4) * 8;                                   // + ks*16
    int b_row = warp_n * 32 + (lane & 7) + (lane >> 4) * 8;        // + j*16
    int b_k8  = ((lane >> 3) & 1) * 8;                             // + ks*16

    float acc[4][4][4];
#pragma unroll
    for (int i = 0; i < 4; i++)
#pragma unroll
        for (int j = 0; j < 4; j++)
#pragma unroll
            for (int c = 0; c < 4; c++) acc[i][j][c] = 0.f;

    int nkt = kChunk >> 5;
    prefetch(0, 0);
    CP_COMMIT();

    for (int kt = 0; kt < nkt; kt++) {
        int cur = kt & 1;
        if (kt + 1 < nkt) { prefetch(kt + 1, cur ^ 1); CP_COMMIT(); CP_WAIT1(); }
        else { CP_WAIT0(); }
        __syncthreads();

        uint32_t stA_h = sb + cur * STAGE_B;
        uint32_t stA_l = stA_h + TILE_B;
        uint32_t stB_h = stA_h + 2 * TILE_B;
        uint32_t stB_l = stA_h + 3 * TILE_B;

#pragma unroll
        for (int ks = 0; ks < 2; ks++) {
            uint32_t ah[4][4], al[4][4], bh[4][2], bl[4][2];
            int ak = ks * 16 + a_k8;
            int bk = ks * 16 + b_k8;
#pragma unroll
            for (int mi = 0; mi < 4; mi++) {
                uint32_t ad = (uint32_t)((a_row + mi * 16) * 80 + ak * 2);
                ldsm_x4(ah[mi], stA_h + ad);
                ldsm_x4(al[mi], stA_l + ad);
            }
#pragma unroll
            for (int j = 0; j < 2; j++) {
                uint32_t bd = (uint32_t)((b_row + j * 16) * 80 + bk * 2);
                uint32_t t[4];
                ldsm_x4(t, stB_h + bd);
                bh[2 * j][0] = t[0]; bh[2 * j][1] = t[1];
                bh[2 * j + 1][0] = t[2]; bh[2 * j + 1][1] = t[3];
                ldsm_x4(t, stB_l + bd);
                bl[2 * j][0] = t[0]; bl[2 * j][1] = t[1];
                bl[2 * j + 1][0] = t[2]; bl[2 * j + 1][1] = t[3];
            }
#pragma unroll
            for (int mi = 0; mi < 4; mi++)
#pragma unroll
                for (int ni = 0; ni < 4; ni++) {
                    mma16816(acc[mi][ni], ah[mi], bh[ni]);
                    mma16816(acc[mi][ni], ah[mi], bl[ni]);
                    mma16816(acc[mi][ni], al[mi], bh[ni]);
                }
        }
        __syncthreads();
    }

    // ---- epilogue ----
    long outOff = (flags & GF_SPLIT) ? (long)blockIdx.z * Mr * N : 0;
    long rEBase = rowBase + warp_m * 64 + (lane >> 2);
    int  cEBase = colBase + warp_n * 32 + (lane & 3) * 2;
#pragma unroll
    for (int mi = 0; mi < 4; mi++) {
#pragma unroll
        for (int hh = 0; hh < 2; hh++) {
            long r = rEBase + mi * 16 + hh * 8;
#pragma unroll
            for (int ni = 0; ni < 4; ni++) {
                int cc = cEBase + ni * 8;
                float v0 = acc[mi][ni][hh * 2 + 0];
                float v1 = acc[mi][ni][hh * 2 + 1];
                if (flags & GF_BIAS) { v0 += __ldg(&bias[cc]); v1 += __ldg(&bias[cc + 1]); }
                if (flags & GF_RESID) {
                    float2 rv = *reinterpret_cast<const float2*>(&resid[r * N + cc]);
                    v0 += rv.x; v1 += rv.y;
                }
                if (flags & GF_RELU) { v0 = fmaxf(v0, 0.f); v1 = fmaxf(v1, 0.f); }
                if (flags & GF_OUTF)
                    *reinterpret_cast<float2*>(&Cf[outOff + r * N + cc]) = make_float2(v0, v1);
                if (flags & GF_OUTBF) {
                    __nv_bfloat16 h0, l0, h1, l1;
                    fsplit(v0, h0, l0); fsplit(v1, h1, l1);
                    *reinterpret_cast<__nv_bfloat162*>(&Chi[r * N + cc]) = __halves2bfloat162(h0, h1);
                    *reinterpret_cast<__nv_bfloat162*>(&Clo[r * N + cc]) = __halves2bfloat162(l0, l1);
                }
            }
        }
    }
}

// ===========================================================================
// Conversion kernels
// ===========================================================================
__global__ void cvt_split_k(const float* __restrict__ in, __nv_bfloat16* __restrict__ oh,
                            __nv_bfloat16* __restrict__ ol, long n4)
{
    long i = (long)blockIdx.x * 256 + threadIdx.x;
    if (i >= n4) return;
    float4 v = reinterpret_cast<const float4*>(in)[i];
    __nv_bfloat16 h0, l0, h1, l1, h2, l2, h3, l3;
    fsplit(v.x, h0, l0); fsplit(v.y, h1, l1); fsplit(v.z, h2, l2); fsplit(v.w, h3, l3);
    long e = i * 4;
    *reinterpret_cast<__nv_bfloat162*>(&oh[e])     = __halves2bfloat162(h0, h1);
    *reinterpret_cast<__nv_bfloat162*>(&oh[e + 2]) = __halves2bfloat162(h2, h3);
    *reinterpret_cast<__nv_bfloat162*>(&ol[e])     = __halves2bfloat162(l0, l1);
    *reinterpret_cast<__nv_bfloat162*>(&ol[e + 2]) = __halves2bfloat162(l2, l3);
}

__global__ void xm_split_k(const float* __restrict__ x, __nv_bfloat16* __restrict__ oh,
                           __nv_bfloat16* __restrict__ ol)
{
    int i = blockIdx.x * 256 + threadIdx.x;
    int f4 = i & 31, m = (i >> 5) & 63, t = (i >> 11) & 255, b = i >> 19;
    float4 v = *reinterpret_cast<const float4*>(
        &x[((long)(b * 256 + t) * 64 + m) * 128 + f4 * 4]);
    long e = (long)(b * 64 + m) * 32768 + t * 128 + f4 * 4;
    __nv_bfloat16 h0, l0, h1, l1, h2, l2, h3, l3;
    fsplit(v.x, h0, l0); fsplit(v.y, h1, l1); fsplit(v.z, h2, l2); fsplit(v.w, h3, l3);
    *reinterpret_cast<__nv_bfloat162*>(&oh[e])     = __halves2bfloat162(h0, h1);
    *reinterpret_cast<__nv_bfloat162*>(&oh[e + 2]) = __halves2bfloat162(h2, h3);
    *reinterpret_cast<__nv_bfloat162*>(&ol[e])     = __halves2bfloat162(l0, l1);
    *reinterpret_cast<__nv_bfloat162*>(&ol[e + 2]) = __halves2bfloat162(l2, l3);
}

__global__ void tsplit_k(const float* __restrict__ W, __nv_bfloat16* __restrict__ oh,
                         __nv_bfloat16* __restrict__ ol, int K, int N)
{
    __shared__ float tile[32][33];
    int bx = blockIdx.x * 32, by = blockIdx.y * 32;
    int tx = threadIdx.x, ty = threadIdx.y;
#pragma unroll
    for (int i = 0; i < 32; i += 8)
        tile[ty + i][tx] = W[(long)(by + ty + i) * N + bx + tx];
    __syncthreads();
#pragma unroll
    for (int i = 0; i < 32; i += 8) {
        int n = bx + ty + i, k = by + tx;
        float v = tile[tx][ty + i];
        __nv_bfloat16 h, l;
        fsplit(v, h, l);
        oh[(long)n * K + k] = h;
        ol[(long)n * K + k] = l;
    }
}

__global__ void im2col_split_k(const float* __restrict__ x, __nv_bfloat16* __restrict__ oh,
                               __nv_bfloat16* __restrict__ ol)
{
    long idx = (long)blockIdx.x * 256 + threadIdx.x;   // ROWS*9*16
    int ch8 = idx & 15;
    long t2 = idx >> 4;
    int tap = (int)(t2 % 9);
    long r = t2 / 9;
    int m = r & 63, t = (int)((r >> 6) & 255), b = (int)(r >> 14);
    int ts = t + tap / 3 - 1, ms = m + tap % 3 - 1;
    float4 v0 = make_float4(0.f, 0.f, 0.f, 0.f), v1 = v0;
    if ((unsigned)ts < 256u && (unsigned)ms < 64u) {
        const float* src = &x[((long)(b * 256 + ts) * 64 + ms) * 128 + ch8 * 8];
        v0 = *reinterpret_cast<const float4*>(src);
        v1 = *reinterpret_cast<const float4*>(src + 4);
    }
    long e = r * KCONV + tap * 128 + ch8 * 8;
    __nv_bfloat16 h[8], l[8];
    fsplit(v0.x, h[0], l[0]); fsplit(v0.y, h[1], l[1]);
    fsplit(v0.z, h[2], l[2]); fsplit(v0.w, h[3], l[3]);
    fsplit(v1.x, h[4], l[4]); fsplit(v1.y, h[5], l[5]);
    fsplit(v1.z, h[6], l[6]); fsplit(v1.w, h[7], l[7]);
#pragma unroll
    for (int j = 0; j < 8; j += 2) {
        *reinterpret_cast<__nv_bfloat162*>(&oh[e + j]) = __halves2bfloat162(h[j], h[j + 1]);
        *reinterpret_cast<__nv_bfloat162*>(&ol[e + j]) = __halves2bfloat162(l[j], l[j + 1]);
    }
}

__global__ void reduce_bias_k(const float* __restrict__ Cp, const float* __restrict__ bias,
                              float* __restrict__ C, int Mr, int N, int S)
{
    int i4 = blockIdx.x * 256 + threadIdx.x;
    long total = (long)Mr * N / 4;
    if (i4 >= total) return;
    long idx = (long)i4 * 4;
    float4 s = *reinterpret_cast<const float4*>(&bias[idx % N]);
    for (int z = 0; z < S; z++) {
        float4 p = *reinterpret_cast<const float4*>(&Cp[(long)z * Mr * N + idx]);
        s.x += p.x; s.y += p.y; s.z += p.z; s.w += p.w;
    }
    *reinterpret_cast<float4*>(&C[idx]) = s;
}

// ===========================================================================
// Softmax kernels
// ===========================================================================
__global__ void at_softmax_k(const float* __restrict__ qt, const float* __restrict__ kt,
                             float* __restrict__ at)
{
    __shared__ float qv[64];
    __shared__ float red[256];
    int q = blockIdx.x, bh = blockIdx.y;
    int b = bh >> 3, h = bh & 7;
    int tid = threadIdx.x;
    if (tid < 64) qv[tid] = qt[(long)(b * 256 + q) * 512 + h * 64 + tid];
    __syncthreads();
    const float* kr = kt + (long)(b * 256 + tid) * 512 + h * 64;
    float s = 0.f;
#pragma unroll 8
    for (int u = 0; u < 64; u++) s += qv[u] * kr[u];
    s *= 0.125f;
    red[tid] = s; __syncthreads();
    for (int st = 128; st > 0; st >>= 1) {
        if (tid < st) red[tid] = fmaxf(red[tid], red[tid + st]);
        __syncthreads();
    }
    float mx = red[0]; __syncthreads();
    float e = __expf(s - mx);
    red[tid] = e; __syncthreads();
    for (int st = 128; st > 0; st >>= 1) {
        if (tid < st) red[tid] += red[tid + st];
        __syncthreads();
    }
    at[((long)bh * 256 + q) * 256 + tid] = e / red[0];
}

__global__ void am_softmax_k(const float* __restrict__ qm, const float* __restrict__ km,
                             float* __restrict__ am)
{
    __shared__ float qv[64];
    __shared__ float red[64];
    int q = blockIdx.x, bh = blockIdx.y;
    int b = bh >> 3, h = bh & 7;
    int tid = threadIdx.x;
    qv[tid] = qm[(long)(b * 64 + q) * 512 + h * 64 + tid];
    __syncthreads();
    const float* kr = km + (long)(b * 64 + tid) * 512 + h * 64;
    float s = 0.f;
#pragma unroll 8
    for (int u = 0; u < 64; u++) s += qv[u] * kr[u];
    s *= 0.125f;
    red[tid] = s; __syncthreads();
    for (int st = 32; st > 0; st >>= 1) {
        if (tid < st) red[tid] = fmaxf(red[tid], red[tid + st]);
        __syncthreads();
    }
    float mx = red[0]; __syncthreads();
    float e = __expf(s - mx);
    red[tid] = e; __syncthreads();
    for (int st = 32; st > 0; st >>= 1) {
        if (tid < st) red[tid] += red[tid + st];
        __syncthreads();
    }
    am[((long)bh * 64 + q) * 64 + tid] = e / red[0];
}

// ===========================================================================
// Attention apply (SIMT 64x64)
// ===========================================================================
__device__ __forceinline__ void tile_fma(const float (&As)[16][68],
                                         const float (&Bs)[16][64],
                                         int r0, int c0, float (&acc)[4][4])
{
#pragma unroll
    for (int kk = 0; kk < 16; kk++) {
        float4 a4 = *reinterpret_cast<const float4*>(&As[kk][r0]);
        float4 b4 = *reinterpret_cast<const float4*>(&Bs[kk][c0]);
        float aa[4] = {a4.x, a4.y, a4.z, a4.w};
        float bb[4] = {b4.x, b4.y, b4.z, b4.w};
#pragma unroll
        for (int i = 0; i < 4; i++)
#pragma unroll
            for (int j = 0; j < 4; j++)
                acc[i][j] += aa[i] * bb[j];
    }
}

__global__ void at_v_k(const float* __restrict__ at, const float* __restrict__ v,
                       float* __restrict__ tmp)
{
    __shared__ __align__(16) float As[16][68];
    __shared__ __align__(16) float Bs[16][64];
    int tid = threadIdx.x;
    int bh = blockIdx.z;
    int b = bh >> 3, h = bh & 7;
    const float* A = at + (long)bh * 65536;
    int rowBase = blockIdx.y * 64, colBase = blockIdx.x * 64;
    int ar = tid >> 2, ac = (tid & 3) << 2;
    int br = tid >> 4, bc = (tid & 15) << 2;
    float acc[4][4] = {};
    for (int k0 = 0; k0 < 256; k0 += 16) {
        float4 av = *reinterpret_cast<const float4*>(&A[(rowBase + ar) * 256 + k0 + ac]);
        As[ac + 0][ar] = av.x; As[ac + 1][ar] = av.y;
        As[ac + 2][ar] = av.z; As[ac + 3][ar] = av.w;
        int k = k0 + br;
        int j = colBase + bc;
        int m = j >> 4, d = j & 15;
        *reinterpret_cast<float4*>(&Bs[br][bc]) =
            *reinterpret_cast<const float4*>(
                &v[((long)(b * 256 + k) * 64 + m) * 128 + h * 16 + d]);
        __syncthreads();
        tile_fma(As, Bs, (tid >> 4) << 2, (tid & 15) << 2, acc);
        __syncthreads();
    }
    int r0 = (tid >> 4) << 2, c0 = (tid & 15) << 2;
#pragma unroll
    for (int i = 0; i < 4; i++) {
        float4 o = make_float4(acc[i][0], acc[i][1], acc[i][2], acc[i][3]);
        *reinterpret_cast<float4*>(
            &tmp[(long)bh * 262144 + (rowBase + r0 + i) * 1024 + colBase + c0]) = o;
    }
}

__global__ void am_tmp_k(const float* __restrict__ am, const float* __restrict__ tmp,
                         __nv_bfloat16* __restrict__ ah, __nv_bfloat16* __restrict__ al)
{
    __shared__ __align__(16) float As[16][68];
    __shared__ __align__(16) float Bs[16][64];
    int tid = threadIdx.x;
    int bh = blockIdx.z;
    int b = bh >> 3, h = bh & 7;
    const float* A = am + (long)bh * 4096;
    int colBase = blockIdx.x * 64;
    int ar = tid >> 2, ac = (tid & 3) << 2;
    int br = tid >> 4, bc = (tid & 15) << 2;
    float acc[4][4] = {};
    for (int k0 = 0; k0 < 64; k0 += 16) {
        float4 av = *reinterpret_cast<const float4*>(&A[ar * 64 + k0 + ac]);
        As[ac + 0][ar] = av.x; As[ac + 1][ar] = av.y;
        As[ac + 2][ar] = av.z; As[ac + 3][ar] = av.w;
        int n = k0 + br;
        int j = colBase + bc;
        int q = j >> 4, d = j & 15;
        *reinterpret_cast<float4*>(&Bs[br][bc]) =
            *reinterpret_cast<const float4*>(
                &tmp[(long)bh * 262144 + q * 1024 + n * 16 + d]);
        __syncthreads();
        tile_fma(As, Bs, (tid >> 4) << 2, (tid & 15) << 2, acc);
        __syncthreads();
    }
    int r0 = (tid >> 4) << 2, c0 = (tid & 15) << 2;
    int j0 = colBase + c0;
    int q = j0 >> 4, d0 = j0 & 15;
#pragma unroll
    for (int i = 0; i < 4; i++) {
        int m = r0 + i;
        long e = ((long)(b * 256 + q) * 64 + m) * 128 + h * 16 + d0;
        __nv_bfloat16 h0, l0, h1, l1, h2, l2, h3, l3;
        fsplit(acc[i][0], h0, l0); fsplit(acc[i][1], h1, l1);
        fsplit(acc[i][2], h2, l2); fsplit(acc[i][3], h3, l3);
        *reinterpret_cast<__nv_bfloat162*>(&ah[e])     = __halves2bfloat162(h0, h1);
        *reinterpret_cast<__nv_bfloat162*>(&ah[e + 2]) = __halves2bfloat162(h2, h3);
        *reinterpret_cast<__nv_bfloat162*>(&al[e])     = __halves2bfloat162(l0, l1);
        *reinterpret_cast<__nv_bfloat162*>(&al[e + 2]) = __halves2bfloat162(l2, l3);
    }
}

// ===========================================================================
// LayerNorm (optionally emits bf16 hi/lo)
// ===========================================================================
__global__ void layernorm_k(const float* __restrict__ y, const float* __restrict__ gg,
                            const float* __restrict__ bb, float* __restrict__ out,
                            __nv_bfloat16* __restrict__ oh, __nv_bfloat16* __restrict__ ol)
{
    int row = blockIdx.x * 4 + (threadIdx.x >> 5);
    int lane = threadIdx.x & 31;
    long base = (long)row * 128 + lane * 4;
    float4 v = *reinterpret_cast<const float4*>(&y[base]);
    float s = v.x + v.y + v.z + v.w;
#pragma unroll
    for (int o = 16; o > 0; o >>= 1) s += __shfl_xor_sync(0xffffffffu, s, o);
    float mean = s * (1.0f / 128.0f);
    float dx = (v.x - mean) * (v.x - mean) + (v.y - mean) * (v.y - mean) +
               (v.z - mean) * (v.z - mean) + (v.w - mean) * (v.w - mean);
#pragma unroll
    for (int o = 16; o > 0; o >>= 1) dx += __shfl_xor_sync(0xffffffffu, dx, o);
    float rstd = rsqrtf(dx * (1.0f / 128.0f) + 1e-6f);
    float4 g4 = *reinterpret_cast<const float4*>(&gg[lane * 4]);
    float4 b4 = *reinterpret_cast<const float4*>(&bb[lane * 4]);
    float4 o4;
    o4.x = (v.x - mean) * rstd * g4.x + b4.x;
    o4.y = (v.y - mean) * rstd * g4.y + b4.y;
    o4.z = (v.z - mean) * rstd * g4.z + b4.z;
    o4.w = (v.w - mean) * rstd * g4.w + b4.w;
    *reinterpret_cast<float4*>(&out[base]) = o4;
    if (oh) {
        __nv_bfloat16 h0, l0, h1, l1, h2, l2, h3, l3;
        fsplit(o4.x, h0, l0); fsplit(o4.y, h1, l1);
        fsplit(o4.z, h2, l2); fsplit(o4.w, h3, l3);
        *reinterpret_cast<__nv_bfloat162*>(&oh[base])     = __halves2bfloat162(h0, h1);
        *reinterpret_cast<__nv_bfloat162*>(&oh[base + 2]) = __halves2bfloat162(h2, h3);
        *reinterpret_cast<__nv_bfloat162*>(&ol[base])     = __halves2bfloat162(l0, l1);
        *reinterpret_cast<__nv_bfloat162*>(&ol[base + 2]) = __halves2bfloat162(l2, l3);
    }
}

// ---------------------------------------------------------------------------
// Launch
// ---------------------------------------------------------------------------
extern "C" void kernel_launch(void* const* d_in, const int* in_sizes, int n_in,
                              void* d_out, int out_size)
{
    const float* x    = (const float*)d_in[0];
    const float* qt_w = (const float*)d_in[1];
    const float* qt_b = (const float*)d_in[2];
    const float* kt_w = (const float*)d_in[3];
    const float* kt_b = (const float*)d_in[4];
    const float* qm_w = (const float*)d_in[5];
    const float* qm_b = (const float*)d_in[6];
    const float* km_w = (const float*)d_in[7];
    const float* km_b = (const float*)d_in[8];
    const float* v_k  = (const float*)d_in[9];
    const float* v_b  = (const float*)d_in[10];
    const float* o_w  = (const float*)d_in[11];
    const float* o_b  = (const float*)d_in[12];
    const float* f1_w = (const float*)d_in[13];
    const float* f1_b = (const float*)d_in[14];
    const float* f2_w = (const float*)d_in[15];
    const float* f2_b = (const float*)d_in[16];
    const float* ln1g = (const float*)d_in[17];
    const float* ln1b = (const float*)d_in[18];
    const float* ln2g = (const float*)d_in[19];
    const float* ln2b = (const float*)d_in[20];
    float* out = (float*)d_out;

    cudaFuncSetAttribute(mma_gemm, cudaFuncAttributeMaxDynamicSharedMemorySize, MMA_SMEM);

    float *qt, *kt, *qm, *km, *v, *at, *am, *tmp, *y1, *o1, *y2, *part;
    cudaGetSymbolAddress((void**)&qt,   g_qt);
    cudaGetSymbolAddress((void**)&kt,   g_kt);
    cudaGetSymbolAddress((void**)&qm,   g_qm);
    cudaGetSymbolAddress((void**)&km,   g_km);
    cudaGetSymbolAddress((void**)&v,    g_v);
    cudaGetSymbolAddress((void**)&at,   g_at);
    cudaGetSymbolAddress((void**)&am,   g_am);
    cudaGetSymbolAddress((void**)&tmp,  g_tmp);
    cudaGetSymbolAddress((void**)&y1,   g_y1);
    cudaGetSymbolAddress((void**)&o1,   g_out1);
    cudaGetSymbolAddress((void**)&y2,   g_y2);
    cudaGetSymbolAddress((void**)&part, g_part);

    __nv_bfloat16 *xh, *xl, *xmh, *xml, *qtwh, *qtwl, *ktwh, *ktwl, *qmwh, *qmwl,
        *kmwh, *kmwl, *f1wh, *f1wl, *f2wh, *f2wl, *owh, *owl, *vwh, *vwl,
        *im2h, *im2l, *o1h, *o1l, *hhh, *hhl, *ath, *atl;
    cudaGetSymbolAddress((void**)&xh,   g_xh);   cudaGetSymbolAddress((void**)&xl,   g_xl);
    cudaGetSymbolAddress((void**)&xmh,  g_xmh);  cudaGetSymbolAddress((void**)&xml,  g_xml);
    cudaGetSymbolAddress((void**)&qtwh, g_qtwh); cudaGetSymbolAddress((void**)&qtwl, g_qtwl);
    cudaGetSymbolAddress((void**)&ktwh, g_ktwh); cudaGetSymbolAddress((void**)&ktwl, g_ktwl);
    cudaGetSymbolAddress((void**)&qmwh, g_qmwh); cudaGetSymbolAddress((void**)&qmwl, g_qmwl);
    cudaGetSymbolAddress((void**)&kmwh, g_kmwh); cudaGetSymbolAddress((void**)&kmwl, g_kmwl);
    cudaGetSymbolAddress((void**)&f1wh, g_f1wh); cudaGetSymbolAddress((void**)&f1wl, g_f1wl);
    cudaGetSymbolAddress((void**)&f2wh, g_f2wh); cudaGetSymbolAddress((void**)&f2wl, g_f2wl);
    cudaGetSymbolAddress((void**)&owh,  g_owh);  cudaGetSymbolAddress((void**)&owl,  g_owl);
    cudaGetSymbolAddress((void**)&vwh,  g_vwh);  cudaGetSymbolAddress((void**)&vwl,  g_vwl);
    cudaGetSymbolAddress((void**)&im2h, g_im2h); cudaGetSymbolAddress((void**)&im2l, g_im2l);
    cudaGetSymbolAddress((void**)&o1h,  g_o1h);  cudaGetSymbolAddress((void**)&o1l,  g_o1l);
    cudaGetSymbolAddress((void**)&hhh,  g_hhh);  cudaGetSymbolAddress((void**)&hhl,  g_hhl);
    cudaGetSymbolAddress((void**)&ath,  g_ath);  cudaGetSymbolAddress((void**)&atl,  g_atl);

    // ---- operand conversion ----
    cvt_split_k<<<16384, 256>>>(x, xh, xl, (long)BT * 8192 / 4);
    xm_split_k<<<16384, 256>>>(x, xmh, xml);
    tsplit_k<<<dim3(16, 256),  dim3(32, 8)>>>(qt_w, qtwh, qtwl, 8192, 512);
    tsplit_k<<<dim3(16, 256),  dim3(32, 8)>>>(kt_w, ktwh, ktwl, 8192, 512);
    tsplit_k<<<dim3(16, 1024), dim3(32, 8)>>>(qm_w, qmwh, qmwl, 32768, 512);
    tsplit_k<<<dim3(16, 1024), dim3(32, 8)>>>(km_w, kmwh, kmwl, 32768, 512);
    tsplit_k<<<dim3(16, 4),    dim3(32, 8)>>>(f1_w, f1wh, f1wl, 128, 512);
    tsplit_k<<<dim3(4, 16),    dim3(32, 8)>>>(f2_w, f2wh, f2wl, 512, 128);
    tsplit_k<<<dim3(4, 4),     dim3(32, 8)>>>(o_w,  owh,  owl,  128, 128);
    tsplit_k<<<dim3(4, 36),    dim3(32, 8)>>>(v_k,  vwh,  vwl,  1152, 128);
    im2col_split_k<<<73728, 256>>>(x, im2h, im2l);

    // ---- projections (HMMA, split-K) ----
    mma_gemm<<<dim3(4, 16, 4), 256, MMA_SMEM>>>(
        xh, xl, qtwh, qtwl, nullptr, nullptr, part, nullptr, nullptr,
        2048, 512, 8192, 2048, GF_OUTF | GF_SPLIT);
    reduce_bias_k<<<1024, 256>>>(part, qt_b, qt, 2048, 512, 4);
    mma_gemm<<<dim3(4, 16, 4), 256, MMA_SMEM>>>(
        xh, xl, ktwh, ktwl, nullptr, nullptr, part, nullptr, nullptr,
        2048, 512, 8192, 2048, GF_OUTF | GF_SPLIT);
    reduce_bias_k<<<1024, 256>>>(part, kt_b, kt, 2048, 512, 4);
    mma_gemm<<<dim3(4, 4, 16), 256, MMA_SMEM>>>(
        xmh, xml, qmwh, qmwl, nullptr, nullptr, part, nullptr, nullptr,
        512, 512, 32768, 2048, GF_OUTF | GF_SPLIT);
    reduce_bias_k<<<256, 256>>>(part, qm_b, qm, 512, 512, 16);
    mma_gemm<<<dim3(4, 4, 16), 256, MMA_SMEM>>>(
        xmh, xml, kmwh, kmwl, nullptr, nullptr, part, nullptr, nullptr,
        512, 512, 32768, 2048, GF_OUTF | GF_SPLIT);
    reduce_bias_k<<<256, 256>>>(part, km_b, km, 512, 512, 16);

    // ---- conv (im2col GEMM) ----
    mma_gemm<<<dim3(1, 1024, 1), 256, MMA_SMEM>>>(
        im2h, im2l, vwh, vwl, v_b, nullptr, v, nullptr, nullptr,
        ROWS, 128, KCONV, (int)KCONV, GF_BIAS | GF_OUTF);

    // ---- attention ----
    at_softmax_k<<<dim3(256, 64), 256>>>(qt, kt, at);
    am_softmax_k<<<dim3(64, 64), 64>>>(qm, km, am);
    at_v_k<<<dim3(16, 4, 64), 256>>>(at, v, tmp);
    am_tmp_k<<<dim3(64, 1, 64), 256>>>(am, tmp, ath, atl);

    // ---- output dense + residual, LN1 ----
    mma_gemm<<<dim3(1, 1024, 1), 256, MMA_SMEM>>>(
        ath, atl, owh, owl, o_b, x, y1, nullptr, nullptr,
        ROWS, 128, 128, 128, GF_BIAS | GF_RESID | GF_OUTF);
    layernorm_k<<<32768, 128>>>(y1, ln1g, ln1b, o1, o1h, o1l);

    // ---- FFN ----
    mma_gemm<<<dim3(4, 1024, 1), 256, MMA_SMEM>>>(
        o1h, o1l, f1wh, f1wl, f1_b, nullptr, nullptr, hhh, hhl,
        ROWS, 512, 128, 128, GF_BIAS | GF_RELU | GF_OUTBF);
    mma_gemm<<<dim3(1, 1024, 1), 256, MMA_SMEM>>>(
        hhh, hhl, f2wh, f2wl, f2_b, o1, y2, nullptr, nullptr,
        ROWS, 128, 512, 512, GF_BIAS | GF_RESID | GF_OUTF);
    layernorm_k<<<32768, 128>>>(y2, ln2g, ln2b, out, nullptr, nullptr);
}

// round 13
// speedup vs baseline: 1.7335x; 1.0940x over previous
#include <cuda_runtime.h>
#include <cuda_bf16.h>
#include <cstdint>

// ---------------------------------------------------------------------------
// EncoderLayer: B=8, T=256, M=64, F=128, H=8, DV=16, TU=MU=64, DFF=512
// Round 11: HMMA bf16 3-term GEMMs; conv now implicit-im2col (A windows read
// straight from L2-resident split x). Launches reordered so ncu -s 5 profiles
// the first big projection GEMM.
// ---------------------------------------------------------------------------

static constexpr int B_ = 8, T_ = 256, M_ = 64, F_ = 128;
static constexpr int H_ = 8, DV_ = 16, DFF_ = 512;
static constexpr int ROWS = B_ * T_ * M_;   // 131072
static constexpr int BT  = B_ * T_;         // 2048
static constexpr int HTU = 512;
static constexpr long KCONV = 1152;         // 9 taps * 128 ch

// ---- fp32 scratch ----
__device__ float g_qt  [BT * HTU];
__device__ float g_kt  [BT * HTU];
__device__ float g_qm  [B_ * M_ * HTU];
__device__ float g_km  [B_ * M_ * HTU];
__device__ float g_v   [ROWS * F_];
__device__ float g_at  [B_ * H_ * T_ * T_];
__device__ float g_am  [B_ * H_ * M_ * M_];
__device__ float g_tmp [(long)B_ * H_ * T_ * M_ * DV_];
__device__ float g_y1  [ROWS * F_];
__device__ float g_out1[ROWS * F_];
__device__ float g_y2  [ROWS * F_];
__device__ float g_part[16 * 512 * 512];    // split-K partials

// ---- bf16 hi/lo operands ----
__device__ __nv_bfloat16 g_xh  [(long)BT * 8192],  g_xl  [(long)BT * 8192];
__device__ __nv_bfloat16 g_xmh [(long)512 * 32768], g_xml [(long)512 * 32768];
__device__ __nv_bfloat16 g_qtwh[(long)512 * 8192],  g_qtwl[(long)512 * 8192];
__device__ __nv_bfloat16 g_ktwh[(long)512 * 8192],  g_ktwl[(long)512 * 8192];
__device__ __nv_bfloat16 g_qmwh[(long)512 * 32768], g_qmwl[(long)512 * 32768];
__device__ __nv_bfloat16 g_kmwh[(long)512 * 32768], g_kmwl[(long)512 * 32768];
__device__ __nv_bfloat16 g_f1wh[512 * 128], g_f1wl[512 * 128];
__device__ __nv_bfloat16 g_f2wh[128 * 512], g_f2wl[128 * 512];
__device__ __nv_bfloat16 g_owh [128 * 128], g_owl [128 * 128];
__device__ __nv_bfloat16 g_vwh [128 * 1152], g_vwl[128 * 1152];
__device__ __nv_bfloat16 g_o1h [(long)ROWS * 128],  g_o1l [(long)ROWS * 128];
__device__ __nv_bfloat16 g_hhh [(long)ROWS * 512],  g_hhl [(long)ROWS * 512];
__device__ __nv_bfloat16 g_ath [(long)ROWS * 128],  g_atl [(long)ROWS * 128];

// ===========================================================================
// PTX helpers (arch-generic sm_80+)
// ===========================================================================
__device__ __forceinline__ uint32_t smem_to_u32(const void* p) {
    uint32_t a;
    asm("{ .reg .u64 t; cvta.to.shared.u64 t, %1; cvt.u32.u64 %0, t; }" : "=r"(a) : "l"(p));
    return a;
}
__device__ __forceinline__ void ldsm_x4(uint32_t* r, uint32_t addr) {
    asm volatile("ldmatrix.sync.aligned.m8n8.x4.shared.b16 {%0,%1,%2,%3}, [%4];"
                 : "=r"(r[0]), "=r"(r[1]), "=r"(r[2]), "=r"(r[3]) : "r"(addr));
}
__device__ __forceinline__ void mma16816(float* d, const uint32_t* a, const uint32_t* b) {
    asm volatile("mma.sync.aligned.m16n8k16.row.col.f32.bf16.bf16.f32 "
                 "{%0,%1,%2,%3}, {%4,%5,%6,%7}, {%8,%9}, {%0,%1,%2,%3};"
                 : "+f"(d[0]), "+f"(d[1]), "+f"(d[2]), "+f"(d[3])
                 : "r"(a[0]), "r"(a[1]), "r"(a[2]), "r"(a[3]), "r"(b[0]), "r"(b[1]));
}
#define CP_ASYNC16(sm, gp) \
    asm volatile("cp.async.cg.shared.global [%0], [%1], 16;" :: "r"(sm), "l"(gp))
// zero-fill variant: src-size register (0 => all zeros)
#define CP_ASYNC16Z(sm, gp, ok) \
    asm volatile("{\n\t.reg .pred p;\n\t.reg .s32 sz;\n\t" \
                 "setp.ne.u32 p, %2, 0;\n\tselp.s32 sz, 16, 0, p;\n\t" \
                 "cp.async.cg.shared.global [%0], [%1], 16, sz;\n\t}" \
                 :: "r"(sm), "l"(gp), "r"(ok))
#define CP_COMMIT() asm volatile("cp.async.commit_group;" ::: "memory")
#define CP_WAIT0()  asm volatile("cp.async.wait_group 0;" ::: "memory")
#define CP_WAIT1()  asm volatile("cp.async.wait_group 1;" ::: "memory")

// flags
static constexpr int GF_BIAS = 1, GF_RELU = 2, GF_RESID = 4, GF_OUTF = 8,
                     GF_OUTBF = 16, GF_SPLIT = 32;

// SMEM: 2 stages x 4 tiles (Ah,Al,Bh,Bl), each 128 rows x 40 bf16 (80B rows)
static constexpr int TILE_B   = 128 * 80;        // 10240
static constexpr int STAGE_B  = 4 * TILE_B;      // 40960
static constexpr int MMA_SMEM = 2 * STAGE_B;     // 81920

__device__ __forceinline__ void fsplit(float v, __nv_bfloat16& h, __nv_bfloat16& l) {
    h = __float2bfloat16(v);
    l = __float2bfloat16(v - __bfloat162float(h));
}

// ===========================================================================
// HMMA GEMM: C[Mr,N] = (Ah+Al)[Mr,K] @ (Bh+Bl)[N,K]^T  (3-term hi/lo)
// grid = (N/128, Mr/128, S); block = 256 (8 warps, each 64x32).
// ===========================================================================
__global__ __launch_bounds__(256, 2)
void mma_gemm(const __nv_bfloat16* __restrict__ Ah, const __nv_bfloat16* __restrict__ Al,
              const __nv_bfloat16* __restrict__ Bh, const __nv_bfloat16* __restrict__ Bl,
              const float* __restrict__ bias, const float* __restrict__ resid,
              float* __restrict__ Cf, __nv_bfloat16* __restrict__ Chi,
              __nv_bfloat16* __restrict__ Clo,
              long Mr, int N, long K, int kChunk, int flags)
{
    extern __shared__ char smem[];
    uint32_t sb = smem_to_u32(smem);
    int tid = threadIdx.x, wid = tid >> 5, lane = tid & 31;
    int warp_m = wid >> 2, warp_n = wid & 3;

    long rowBase = (long)blockIdx.y * 128;
    int  colBase = blockIdx.x * 128;
    long kBeg = (long)blockIdx.z * kChunk;

    int lrow = tid >> 1, lhalf = tid & 1;
    const __nv_bfloat16* gA[2] = { Ah + (rowBase + lrow) * K + kBeg,
                                   Al + (rowBase + lrow) * K + kBeg };
    const __nv_bfloat16* gB[2] = { Bh + (long)(colBase + lrow) * K + kBeg,
                                   Bl + (long)(colBase + lrow) * K + kBeg };
    uint32_t soBase = (uint32_t)(lrow * 80 + lhalf * 32);

    auto prefetch = [&](int kt, int st) {
        long off = (long)kt * 32 + lhalf * 16;
        uint32_t s0 = sb + st * STAGE_B + soBase;
        CP_ASYNC16(s0 + 0 * TILE_B,      gA[0] + off);
        CP_ASYNC16(s0 + 0 * TILE_B + 16, gA[0] + off + 8);
        CP_ASYNC16(s0 + 1 * TILE_B,      gA[1] + off);
        CP_ASYNC16(s0 + 1 * TILE_B + 16, gA[1] + off + 8);
        CP_ASYNC16(s0 + 2 * TILE_B,      gB[0] + off);
        CP_ASYNC16(s0 + 2 * TILE_B + 16, gB[0] + off + 8);
        CP_ASYNC16(s0 + 3 * TILE_B,      gB[1] + off);
        CP_ASYNC16(s0 + 3 * TILE_B + 16, gB[1] + off + 8);
    };

    int a_row = warp_m * 64 + (lane & 7) + ((lane >> 3) & 1) * 8;
    int a_k8  = (lane >> 4) * 8;
    int b_row = warp_n * 32 + (lane & 7) + (lane >> 4) * 8;
    int b_k8  = ((lane >> 3) & 1) * 8;

    float acc[4][4][4];
#pragma unroll
    for (int i = 0; i < 4; i++)
#pragma unroll
        for (int j = 0; j < 4; j++)
#pragma unroll
            for (int c = 0; c < 4; c++) acc[i][j][c] = 0.f;

    int nkt = kChunk >> 5;
    prefetch(0, 0);
    CP_COMMIT();

    for (int kt = 0; kt < nkt; kt++) {
        int cur = kt & 1;
        if (kt + 1 < nkt) { prefetch(kt + 1, cur ^ 1); CP_COMMIT(); CP_WAIT1(); }
        else { CP_WAIT0(); }
        __syncthreads();

        uint32_t stA_h = sb + cur * STAGE_B;
        uint32_t stA_l = stA_h + TILE_B;
        uint32_t stB_h = stA_h + 2 * TILE_B;
        uint32_t stB_l = stA_h + 3 * TILE_B;

#pragma unroll
        for (int ks = 0; ks < 2; ks++) {
            uint32_t ah[4][4], al[4][4], bh[4][2], bl[4][2];
            int ak = ks * 16 + a_k8;
            int bk = ks * 16 + b_k8;
#pragma unroll
            for (int mi = 0; mi < 4; mi++) {
                uint32_t ad = (uint32_t)((a_row + mi * 16) * 80 + ak * 2);
                ldsm_x4(ah[mi], stA_h + ad);
                ldsm_x4(al[mi], stA_l + ad);
            }
#pragma unroll
            for (int j = 0; j < 2; j++) {
                uint32_t bd = (uint32_t)((b_row + j * 16) * 80 + bk * 2);
                uint32_t t[4];
                ldsm_x4(t, stB_h + bd);
                bh[2 * j][0] = t[0]; bh[2 * j][1] = t[1];
                bh[2 * j + 1][0] = t[2]; bh[2 * j + 1][1] = t[3];
                ldsm_x4(t, stB_l + bd);
                bl[2 * j][0] = t[0]; bl[2 * j][1] = t[1];
                bl[2 * j + 1][0] = t[2]; bl[2 * j + 1][1] = t[3];
            }
#pragma unroll
            for (int mi = 0; mi < 4; mi++)
#pragma unroll
                for (int ni = 0; ni < 4; ni++) {
                    mma16816(acc[mi][ni], ah[mi], bh[ni]);
                    mma16816(acc[mi][ni], ah[mi], bl[ni]);
                    mma16816(acc[mi][ni], al[mi], bh[ni]);
                }
        }
        __syncthreads();
    }

    long outOff = (flags & GF_SPLIT) ? (long)blockIdx.z * Mr * N : 0;
    long rEBase = rowBase + warp_m * 64 + (lane >> 2);
    int  cEBase = colBase + warp_n * 32 + (lane & 3) * 2;
#pragma unroll
    for (int mi = 0; mi < 4; mi++) {
#pragma unroll
        for (int hh = 0; hh < 2; hh++) {
            long r = rEBase + mi * 16 + hh * 8;
#pragma unroll
            for (int ni = 0; ni < 4; ni++) {
                int cc = cEBase + ni * 8;
                float v0 = acc[mi][ni][hh * 2 + 0];
                float v1 = acc[mi][ni][hh * 2 + 1];
                if (flags & GF_BIAS) { v0 += __ldg(&bias[cc]); v1 += __ldg(&bias[cc + 1]); }
                if (flags & GF_RESID) {
                    float2 rv = *reinterpret_cast<const float2*>(&resid[r * N + cc]);
                    v0 += rv.x; v1 += rv.y;
                }
                if (flags & GF_RELU) { v0 = fmaxf(v0, 0.f); v1 = fmaxf(v1, 0.f); }
                if (flags & GF_OUTF)
                    *reinterpret_cast<float2*>(&Cf[outOff + r * N + cc]) = make_float2(v0, v1);
                if (flags & GF_OUTBF) {
                    __nv_bfloat16 h0, l0, h1, l1;
                    fsplit(v0, h0, l0); fsplit(v1, h1, l1);
                    *reinterpret_cast<__nv_bfloat162*>(&Chi[r * N + cc]) = __halves2bfloat162(h0, h1);
                    *reinterpret_cast<__nv_bfloat162*>(&Clo[r * N + cc]) = __halves2bfloat162(l0, l1);
                }
            }
        }
    }
}

// ===========================================================================
// Implicit-im2col conv GEMM: v[r, n] = sum_tap,c x[b,t+dt-1,m+dm-1,c]*W[n, tap*128+c]
// A windows read from split x (row layout [(b*256+t)][m*128+f]); halo zero-filled
// via cp.async src-size=0. grid = (1, ROWS/128); block = 256.
// ===========================================================================
__global__ __launch_bounds__(256, 2)
void mma_conv(const __nv_bfloat16* __restrict__ xh, const __nv_bfloat16* __restrict__ xl,
              const __nv_bfloat16* __restrict__ Bh, const __nv_bfloat16* __restrict__ Bl,
              const float* __restrict__ bias, float* __restrict__ Cf)
{
    extern __shared__ char smem[];
    uint32_t sb = smem_to_u32(smem);
    int tid = threadIdx.x, wid = tid >> 5, lane = tid & 31;
    int warp_m = wid >> 2, warp_n = wid & 3;
    long rowBase = (long)blockIdx.y * 128;

    int lrow = tid >> 1, lhalf = tid & 1;
    long r = rowBase + lrow;
    int lm = (int)(r & 63), lt = (int)((r >> 6) & 255), lb = (int)(r >> 14);
    const __nv_bfloat16* gB[2] = { Bh + (long)lrow * KCONV, Bl + (long)lrow * KCONV };
    uint32_t soBase = (uint32_t)(lrow * 80 + lhalf * 32);

    auto prefetch = [&](int kt, int st) {
        int k = kt * 32;
        int tap = k >> 7;
        int cofs = (k & 127) + lhalf * 16;
        int ts = lt + tap / 3 - 1, ms = lm + (tap % 3) - 1;
        uint32_t ok = ((unsigned)ts < 256u && (unsigned)ms < 64u) ? 1u : 0u;
        const __nv_bfloat16* pah = xh;
        const __nv_bfloat16* pal = xl;
        if (ok) {
            long ao = (long)(lb * 256 + ts) * 8192 + ms * 128 + cofs;
            pah = xh + ao; pal = xl + ao;
        }
        long boff = (long)k + lhalf * 16;
        uint32_t s0 = sb + st * STAGE_B + soBase;
        CP_ASYNC16Z(s0 + 0 * TILE_B,      pah,     ok);
        CP_ASYNC16Z(s0 + 0 * TILE_B + 16, pah + 8, ok);
        CP_ASYNC16Z(s0 + 1 * TILE_B,      pal,     ok);
        CP_ASYNC16Z(s0 + 1 * TILE_B + 16, pal + 8, ok);
        CP_ASYNC16(s0 + 2 * TILE_B,      gB[0] + boff);
        CP_ASYNC16(s0 + 2 * TILE_B + 16, gB[0] + boff + 8);
        CP_ASYNC16(s0 + 3 * TILE_B,      gB[1] + boff);
        CP_ASYNC16(s0 + 3 * TILE_B + 16, gB[1] + boff + 8);
    };

    int a_row = warp_m * 64 + (lane & 7) + ((lane >> 3) & 1) * 8;
    int a_k8  = (lane >> 4) * 8;
    int b_row = warp_n * 32 + (lane & 7) + (lane >> 4) * 8;
    int b_k8  = ((lane >> 3) & 1) * 8;

    float acc[4][4][4];
#pragma unroll
    for (int i = 0; i < 4; i++)
#pragma unroll
        for (int j = 0; j < 4; j++)
#pragma unroll
            for (int c = 0; c < 4; c++) acc[i][j][c] = 0.f;

    const int nkt = (int)(KCONV >> 5);   // 36
    prefetch(0, 0);
    CP_COMMIT();

    for (int kt = 0; kt < nkt; kt++) {
        int cur = kt & 1;
        if (kt + 1 < nkt) { prefetch(kt + 1, cur ^ 1); CP_COMMIT(); CP_WAIT1(); }
        else { CP_WAIT0(); }
        __syncthreads();

        uint32_t stA_h = sb + cur * STAGE_B;
        uint32_t stA_l = stA_h + TILE_B;
        uint32_t stB_h = stA_h + 2 * TILE_B;
        uint32_t stB_l = stA_h + 3 * TILE_B;

#pragma unroll
        for (int ks = 0; ks < 2; ks++) {
            uint32_t ah[4][4], al[4][4], bh[4][2], bl[4][2];
            int ak = ks * 16 + a_k8;
            int bk = ks * 16 + b_k8;
#pragma unroll
            for (int mi = 0; mi < 4; mi++) {
                uint32_t ad = (uint32_t)((a_row + mi * 16) * 80 + ak * 2);
                ldsm_x4(ah[mi], stA_h + ad);
                ldsm_x4(al[mi], stA_l + ad);
            }
#pragma unroll
            for (int j = 0; j < 2; j++) {
                uint32_t bd = (uint32_t)((b_row + j * 16) * 80 + bk * 2);
                uint32_t t[4];
                ldsm_x4(t, stB_h + bd);
                bh[2 * j][0] = t[0]; bh[2 * j][1] = t[1];
                bh[2 * j + 1][0] = t[2]; bh[2 * j + 1][1] = t[3];
                ldsm_x4(t, stB_l + bd);
                bl[2 * j][0] = t[0]; bl[2 * j][1] = t[1];
                bl[2 * j + 1][0] = t[2]; bl[2 * j + 1][1] = t[3];
            }
#pragma unroll
            for (int mi = 0; mi < 4; mi++)
#pragma unroll
                for (int ni = 0; ni < 4; ni++) {
                    mma16816(acc[mi][ni], ah[mi], bh[ni]);
                    mma16816(acc[mi][ni], ah[mi], bl[ni]);
                    mma16816(acc[mi][ni], al[mi], bh[ni]);
                }
        }
        __syncthreads();
    }

    long rEBase = rowBase + warp_m * 64 + (lane >> 2);
    int  cEBase = warp_n * 32 + (lane & 3) * 2;
#pragma unroll
    for (int mi = 0; mi < 4; mi++) {
#pragma unroll
        for (int hh = 0; hh < 2; hh++) {
            long rr = rEBase + mi * 16 + hh * 8;
#pragma unroll
            for (int ni = 0; ni < 4; ni++) {
                int cc = cEBase + ni * 8;
                float v0 = acc[mi][ni][hh * 2 + 0] + __ldg(&bias[cc]);
                float v1 = acc[mi][ni][hh * 2 + 1] + __ldg(&bias[cc + 1]);
                *reinterpret_cast<float2*>(&Cf[rr * 128 + cc]) = make_float2(v0, v1);
            }
        }
    }
}

// ===========================================================================
// Conversion kernels
// ===========================================================================
__global__ void cvt_split_k(const float* __restrict__ in, __nv_bfloat16* __restrict__ oh,
                            __nv_bfloat16* __restrict__ ol, long n4)
{
    long i = (long)blockIdx.x * 256 + threadIdx.x;
    if (i >= n4) return;
    float4 v = reinterpret_cast<const float4*>(in)[i];
    __nv_bfloat16 h0, l0, h1, l1, h2, l2, h3, l3;
    fsplit(v.x, h0, l0); fsplit(v.y, h1, l1); fsplit(v.z, h2, l2); fsplit(v.w, h3, l3);
    long e = i * 4;
    *reinterpret_cast<__nv_bfloat162*>(&oh[e])     = __halves2bfloat162(h0, h1);
    *reinterpret_cast<__nv_bfloat162*>(&oh[e + 2]) = __halves2bfloat162(h2, h3);
    *reinterpret_cast<__nv_bfloat162*>(&ol[e])     = __halves2bfloat162(l0, l1);
    *reinterpret_cast<__nv_bfloat162*>(&ol[e + 2]) = __halves2bfloat162(l2, l3);
}

__global__ void xm_split_k(const float* __restrict__ x, __nv_bfloat16* __restrict__ oh,
                           __nv_bfloat16* __restrict__ ol)
{
    int i = blockIdx.x * 256 + threadIdx.x;
    int f4 = i & 31, m = (i >> 5) & 63, t = (i >> 11) & 255, b = i >> 19;
    float4 v = *reinterpret_cast<const float4*>(
        &x[((long)(b * 256 + t) * 64 + m) * 128 + f4 * 4]);
    long e = (long)(b * 64 + m) * 32768 + t * 128 + f4 * 4;
    __nv_bfloat16 h0, l0, h1, l1, h2, l2, h3, l3;
    fsplit(v.x, h0, l0); fsplit(v.y, h1, l1); fsplit(v.z, h2, l2); fsplit(v.w, h3, l3);
    *reinterpret_cast<__nv_bfloat162*>(&oh[e])     = __halves2bfloat162(h0, h1);
    *reinterpret_cast<__nv_bfloat162*>(&oh[e + 2]) = __halves2bfloat162(h2, h3);
    *reinterpret_cast<__nv_bfloat162*>(&ol[e])     = __halves2bfloat162(l0, l1);
    *reinterpret_cast<__nv_bfloat162*>(&ol[e + 2]) = __halves2bfloat162(l2, l3);
}

__global__ void tsplit_k(const float* __restrict__ W, __nv_bfloat16* __restrict__ oh,
                         __nv_bfloat16* __restrict__ ol, int K, int N)
{
    __shared__ float tile[32][33];
    int bx = blockIdx.x * 32, by = blockIdx.y * 32;
    int tx = threadIdx.x, ty = threadIdx.y;
#pragma unroll
    for (int i = 0; i < 32; i += 8)
        tile[ty + i][tx] = W[(long)(by + ty + i) * N + bx + tx];
    __syncthreads();
#pragma unroll
    for (int i = 0; i < 32; i += 8) {
        int n = bx + ty + i, k = by + tx;
        float v = tile[tx][ty + i];
        __nv_bfloat16 h, l;
        fsplit(v, h, l);
        oh[(long)n * K + k] = h;
        ol[(long)n * K + k] = l;
    }
}

__global__ void reduce_bias_k(const float* __restrict__ Cp, const float* __restrict__ bias,
                              float* __restrict__ C, int Mr, int N, int S)
{
    int i4 = blockIdx.x * 256 + threadIdx.x;
    long total = (long)Mr * N / 4;
    if (i4 >= total) return;
    long idx = (long)i4 * 4;
    float4 s = *reinterpret_cast<const float4*>(&bias[idx % N]);
    for (int z = 0; z < S; z++) {
        float4 p = *reinterpret_cast<const float4*>(&Cp[(long)z * Mr * N + idx]);
        s.x += p.x; s.y += p.y; s.z += p.z; s.w += p.w;
    }
    *reinterpret_cast<float4*>(&C[idx]) = s;
}

// ===========================================================================
// Softmax kernels
// ===========================================================================
__global__ void at_softmax_k(const float* __restrict__ qt, const float* __restrict__ kt,
                             float* __restrict__ at)
{
    __shared__ float qv[64];
    __shared__ float red[256];
    int q = blockIdx.x, bh = blockIdx.y;
    int b = bh >> 3, h = bh & 7;
    int tid = threadIdx.x;
    if (tid < 64) qv[tid] = qt[(long)(b * 256 + q) * 512 + h * 64 + tid];
    __syncthreads();
    const float* kr = kt + (long)(b * 256 + tid) * 512 + h * 64;
    float s = 0.f;
#pragma unroll 8
    for (int u = 0; u < 64; u++) s += qv[u] * kr[u];
    s *= 0.125f;
    red[tid] = s; __syncthreads();
    for (int st = 128; st > 0; st >>= 1) {
        if (tid < st) red[tid] = fmaxf(red[tid], red[tid + st]);
        __syncthreads();
    }
    float mx = red[0]; __syncthreads();
    float e = __expf(s - mx);
    red[tid] = e; __syncthreads();
    for (int st = 128; st > 0; st >>= 1) {
        if (tid < st) red[tid] += red[tid + st];
        __syncthreads();
    }
    at[((long)bh * 256 + q) * 256 + tid] = e / red[0];
}

__global__ void am_softmax_k(const float* __restrict__ qm, const float* __restrict__ km,
                             float* __restrict__ am)
{
    __shared__ float qv[64];
    __shared__ float red[64];
    int q = blockIdx.x, bh = blockIdx.y;
    int b = bh >> 3, h = bh & 7;
    int tid = threadIdx.x;
    qv[tid] = qm[(long)(b * 64 + q) * 512 + h * 64 + tid];
    __syncthreads();
    const float* kr = km + (long)(b * 64 + tid) * 512 + h * 64;
    float s = 0.f;
#pragma unroll 8
    for (int u = 0; u < 64; u++) s += qv[u] * kr[u];
    s *= 0.125f;
    red[tid] = s; __syncthreads();
    for (int st = 32; st > 0; st >>= 1) {
        if (tid < st) red[tid] = fmaxf(red[tid], red[tid + st]);
        __syncthreads();
    }
    float mx = red[0]; __syncthreads();
    float e = __expf(s - mx);
    red[tid] = e; __syncthreads();
    for (int st = 32; st > 0; st >>= 1) {
        if (tid < st) red[tid] += red[tid + st];
        __syncthreads();
    }
    am[((long)bh * 64 + q) * 64 + tid] = e / red[0];
}

// ===========================================================================
// Attention apply (SIMT 64x64)
// ===========================================================================
__device__ __forceinline__ void tile_fma(const float (&As)[16][68],
                                         const float (&Bs)[16][64],
                                         int r0, int c0, float (&acc)[4][4])
{
#pragma unroll
    for (int kk = 0; kk < 16; kk++) {
        float4 a4 = *reinterpret_cast<const float4*>(&As[kk][r0]);
        float4 b4 = *reinterpret_cast<const float4*>(&Bs[kk][c0]);
        float aa[4] = {a4.x, a4.y, a4.z, a4.w};
        float bb[4] = {b4.x, b4.y, b4.z, b4.w};
#pragma unroll
        for (int i = 0; i < 4; i++)
#pragma unroll
            for (int j = 0; j < 4; j++)
                acc[i][j] += aa[i] * bb[j];
    }
}

__global__ void at_v_k(const float* __restrict__ at, const float* __restrict__ v,
                       float* __restrict__ tmp)
{
    __shared__ __align__(16) float As[16][68];
    __shared__ __align__(16) float Bs[16][64];
    int tid = threadIdx.x;
    int bh = blockIdx.z;
    int b = bh >> 3, h = bh & 7;
    const float* A = at + (long)bh * 65536;
    int rowBase = blockIdx.y * 64, colBase = blockIdx.x * 64;
    int ar = tid >> 2, ac = (tid & 3) << 2;
    int br = tid >> 4, bc = (tid & 15) << 2;
    float acc[4][4] = {};
    for (int k0 = 0; k0 < 256; k0 += 16) {
        float4 av = *reinterpret_cast<const float4*>(&A[(rowBase + ar) * 256 + k0 + ac]);
        As[ac + 0][ar] = av.x; As[ac + 1][ar] = av.y;
        As[ac + 2][ar] = av.z; As[ac + 3][ar] = av.w;
        int k = k0 + br;
        int j = colBase + bc;
        int m = j >> 4, d = j & 15;
        *reinterpret_cast<float4*>(&Bs[br][bc]) =
            *reinterpret_cast<const float4*>(
                &v[((long)(b * 256 + k) * 64 + m) * 128 + h * 16 + d]);
        __syncthreads();
        tile_fma(As, Bs, (tid >> 4) << 2, (tid & 15) << 2, acc);
        __syncthreads();
    }
    int r0 = (tid >> 4) << 2, c0 = (tid & 15) << 2;
#pragma unroll
    for (int i = 0; i < 4; i++) {
        float4 o = make_float4(acc[i][0], acc[i][1], acc[i][2], acc[i][3]);
        *reinterpret_cast<float4*>(
            &tmp[(long)bh * 262144 + (rowBase + r0 + i) * 1024 + colBase + c0]) = o;
    }
}

__global__ void am_tmp_k(const float* __restrict__ am, const float* __restrict__ tmp,
                         __nv_bfloat16* __restrict__ ah, __nv_bfloat16* __restrict__ al)
{
    __shared__ __align__(16) float As[16][68];
    __shared__ __align__(16) float Bs[16][64];
    int tid = threadIdx.x;
    int bh = blockIdx.z;
    int b = bh >> 3, h = bh & 7;
    const float* A = am + (long)bh * 4096;
    int colBase = blockIdx.x * 64;
    int ar = tid >> 2, ac = (tid & 3) << 2;
    int br = tid >> 4, bc = (tid & 15) << 2;
    float acc[4][4] = {};
    for (int k0 = 0; k0 < 64; k0 += 16) {
        float4 av = *reinterpret_cast<const float4*>(&A[ar * 64 + k0 + ac]);
        As[ac + 0][ar] = av.x; As[ac + 1][ar] = av.y;
        As[ac + 2][ar] = av.z; As[ac + 3][ar] = av.w;
        int n = k0 + br;
        int j = colBase + bc;
        int q = j >> 4, d = j & 15;
        *reinterpret_cast<float4*>(&Bs[br][bc]) =
            *reinterpret_cast<const float4*>(
                &tmp[(long)bh * 262144 + q * 1024 + n * 16 + d]);
        __syncthreads();
        tile_fma(As, Bs, (tid >> 4) << 2, (tid & 15) << 2, acc);
        __syncthreads();
    }
    int r0 = (tid >> 4) << 2, c0 = (tid & 15) << 2;
    int j0 = colBase + c0;
    int q = j0 >> 4, d0 = j0 & 15;
#pragma unroll
    for (int i = 0; i < 4; i++) {
        int m = r0 + i;
        long e = ((long)(b * 256 + q) * 64 + m) * 128 + h * 16 + d0;
        __nv_bfloat16 h0, l0, h1, l1, h2, l2, h3, l3;
        fsplit(acc[i][0], h0, l0); fsplit(acc[i][1], h1, l1);
        fsplit(acc[i][2], h2, l2); fsplit(acc[i][3], h3, l3);
        *reinterpret_cast<__nv_bfloat162*>(&ah[e])     = __halves2bfloat162(h0, h1);
        *reinterpret_cast<__nv_bfloat162*>(&ah[e + 2]) = __halves2bfloat162(h2, h3);
        *reinterpret_cast<__nv_bfloat162*>(&al[e])     = __halves2bfloat162(l0, l1);
        *reinterpret_cast<__nv_bfloat162*>(&al[e + 2]) = __halves2bfloat162(l2, l3);
    }
}

// ===========================================================================
// LayerNorm (optionally emits bf16 hi/lo)
// ===========================================================================
__global__ void layernorm_k(const float* __restrict__ y, const float* __restrict__ gg,
                            const float* __restrict__ bb, float* __restrict__ out,
                            __nv_bfloat16* __restrict__ oh, __nv_bfloat16* __restrict__ ol)
{
    int row = blockIdx.x * 4 + (threadIdx.x >> 5);
    int lane = threadIdx.x & 31;
    long base = (long)row * 128 + lane * 4;
    float4 v = *reinterpret_cast<const float4*>(&y[base]);
    float s = v.x + v.y + v.z + v.w;
#pragma unroll
    for (int o = 16; o > 0; o >>= 1) s += __shfl_xor_sync(0xffffffffu, s, o);
    float mean = s * (1.0f / 128.0f);
    float dx = (v.x - mean) * (v.x - mean) + (v.y - mean) * (v.y - mean) +
               (v.z - mean) * (v.z - mean) + (v.w - mean) * (v.w - mean);
#pragma unroll
    for (int o = 16; o > 0; o >>= 1) dx += __shfl_xor_sync(0xffffffffu, dx, o);
    float rstd = rsqrtf(dx * (1.0f / 128.0f) + 1e-6f);
    float4 g4 = *reinterpret_cast<const float4*>(&gg[lane * 4]);
    float4 b4 = *reinterpret_cast<const float4*>(&bb[lane * 4]);
    float4 o4;
    o4.x = (v.x - mean) * rstd * g4.x + b4.x;
    o4.y = (v.y - mean) * rstd * g4.y + b4.y;
    o4.z = (v.z - mean) * rstd * g4.z + b4.z;
    o4.w = (v.w - mean) * rstd * g4.w + b4.w;
    *reinterpret_cast<float4*>(&out[base]) = o4;
    if (oh) {
        __nv_bfloat16 h0, l0, h1, l1, h2, l2, h3, l3;
        fsplit(o4.x, h0, l0); fsplit(o4.y, h1, l1);
        fsplit(o4.z, h2, l2); fsplit(o4.w, h3, l3);
        *reinterpret_cast<__nv_bfloat162*>(&oh[base])     = __halves2bfloat162(h0, h1);
        *reinterpret_cast<__nv_bfloat162*>(&oh[base + 2]) = __halves2bfloat162(h2, h3);
        *reinterpret_cast<__nv_bfloat162*>(&ol[base])     = __halves2bfloat162(l0, l1);
        *reinterpret_cast<__nv_bfloat162*>(&ol[base + 2]) = __halves2bfloat162(l2, l3);
    }
}

// ---------------------------------------------------------------------------
// Launch  (order chosen so ncu -s 5 -c 1 captures the first big mma_gemm)
// ---------------------------------------------------------------------------
extern "C" void kernel_launch(void* const* d_in, const int* in_sizes, int n_in,
                              void* d_out, int out_size)
{
    const float* x    = (const float*)d_in[0];
    const float* qt_w = (const float*)d_in[1];
    const float* qt_b = (const float*)d_in[2];
    const float* kt_w = (const float*)d_in[3];
    const float* kt_b = (const float*)d_in[4];
    const float* qm_w = (const float*)d_in[5];
    const float* qm_b = (const float*)d_in[6];
    const float* km_w = (const float*)d_in[7];
    const float* km_b = (const float*)d_in[8];
    const float* v_k  = (const float*)d_in[9];
    const float* v_b  = (const float*)d_in[10];
    const float* o_w  = (const float*)d_in[11];
    const float* o_b  = (const float*)d_in[12];
    const float* f1_w = (const float*)d_in[13];
    const float* f1_b = (const float*)d_in[14];
    const float* f2_w = (const float*)d_in[15];
    const float* f2_b = (const float*)d_in[16];
    const float* ln1g = (const float*)d_in[17];
    const float* ln1b = (const float*)d_in[18];
    const float* ln2g = (const float*)d_in[19];
    const float* ln2b = (const float*)d_in[20];
    float* out = (float*)d_out;

    cudaFuncSetAttribute(mma_gemm, cudaFuncAttributeMaxDynamicSharedMemorySize, MMA_SMEM);
    cudaFuncSetAttribute(mma_conv, cudaFuncAttributeMaxDynamicSharedMemorySize, MMA_SMEM);

    float *qt, *kt, *qm, *km, *v, *at, *am, *tmp, *y1, *o1, *y2, *part;
    cudaGetSymbolAddress((void**)&qt,   g_qt);
    cudaGetSymbolAddress((void**)&kt,   g_kt);
    cudaGetSymbolAddress((void**)&qm,   g_qm);
    cudaGetSymbolAddress((void**)&km,   g_km);
    cudaGetSymbolAddress((void**)&v,    g_v);
    cudaGetSymbolAddress((void**)&at,   g_at);
    cudaGetSymbolAddress((void**)&am,   g_am);
    cudaGetSymbolAddress((void**)&tmp,  g_tmp);
    cudaGetSymbolAddress((void**)&y1,   g_y1);
    cudaGetSymbolAddress((void**)&o1,   g_out1);
    cudaGetSymbolAddress((void**)&y2,   g_y2);
    cudaGetSymbolAddress((void**)&part, g_part);

    __nv_bfloat16 *xh, *xl, *xmh, *xml, *qtwh, *qtwl, *ktwh, *ktwl, *qmwh, *qmwl,
        *kmwh, *kmwl, *f1wh, *f1wl, *f2wh, *f2wl, *owh, *owl, *vwh, *vwl,
        *o1h, *o1l, *hhh, *hhl, *ath, *atl;
    cudaGetSymbolAddress((void**)&xh,   g_xh);   cudaGetSymbolAddress((void**)&xl,   g_xl);
    cudaGetSymbolAddress((void**)&xmh,  g_xmh);  cudaGetSymbolAddress((void**)&xml,  g_xml);
    cudaGetSymbolAddress((void**)&qtwh, g_qtwh); cudaGetSymbolAddress((void**)&qtwl, g_qtwl);
    cudaGetSymbolAddress((void**)&ktwh, g_ktwh); cudaGetSymbolAddress((void**)&ktwl, g_ktwl);
    cudaGetSymbolAddress((void**)&qmwh, g_qmwh); cudaGetSymbolAddress((void**)&qmwl, g_qmwl);
    cudaGetSymbolAddress((void**)&kmwh, g_kmwh); cudaGetSymbolAddress((void**)&kmwl, g_kmwl);
    cudaGetSymbolAddress((void**)&f1wh, g_f1wh); cudaGetSymbolAddress((void**)&f1wl, g_f1wl);
    cudaGetSymbolAddress((void**)&f2wh, g_f2wh); cudaGetSymbolAddress((void**)&f2wl, g_f2wl);
    cudaGetSymbolAddress((void**)&owh,  g_owh);  cudaGetSymbolAddress((void**)&owl,  g_owl);
    cudaGetSymbolAddress((void**)&vwh,  g_vwh);  cudaGetSymbolAddress((void**)&vwl,  g_vwl);
    cudaGetSymbolAddress((void**)&o1h,  g_o1h);  cudaGetSymbolAddress((void**)&o1l,  g_o1l);
    cudaGetSymbolAddress((void**)&hhh,  g_hhh);  cudaGetSymbolAddress((void**)&hhl,  g_hhl);
    cudaGetSymbolAddress((void**)&ath,  g_ath);  cudaGetSymbolAddress((void**)&atl,  g_atl);

    // 0-4: conversions needed by the first projection GEMM
    cvt_split_k<<<16384, 256>>>(x, xh, xl, (long)BT * 8192 / 4);          // 0
    xm_split_k<<<16384, 256>>>(x, xmh, xml);                              // 1
    tsplit_k<<<dim3(16, 256),  dim3(32, 8)>>>(qt_w, qtwh, qtwl, 8192, 512);   // 2
    tsplit_k<<<dim3(16, 256),  dim3(32, 8)>>>(kt_w, ktwh, ktwl, 8192, 512);   // 3
    tsplit_k<<<dim3(16, 1024), dim3(32, 8)>>>(qm_w, qmwh, qmwl, 32768, 512);  // 4

    // 5: first big GEMM — this is what ncu captures
    mma_gemm<<<dim3(4, 16, 4), 256, MMA_SMEM>>>(
        xh, xl, qtwh, qtwl, nullptr, nullptr, part, nullptr, nullptr,
        2048, 512, 8192, 2048, GF_OUTF | GF_SPLIT);
    reduce_bias_k<<<1024, 256>>>(part, qt_b, qt, 2048, 512, 4);
    mma_gemm<<<dim3(4, 16, 4), 256, MMA_SMEM>>>(
        xh, xl, ktwh, ktwl, nullptr, nullptr, part, nullptr, nullptr,
        2048, 512, 8192, 2048, GF_OUTF | GF_SPLIT);
    reduce_bias_k<<<1024, 256>>>(part, kt_b, kt, 2048, 512, 4);

    tsplit_k<<<dim3(16, 1024), dim3(32, 8)>>>(km_w, kmwh, kmwl, 32768, 512);
    mma_gemm<<<dim3(4, 4, 16), 256, MMA_SMEM>>>(
        xmh, xml, qmwh, qmwl, nullptr, nullptr, part, nullptr, nullptr,
        512, 512, 32768, 2048, GF_OUTF | GF_SPLIT);
    reduce_bias_k<<<256, 256>>>(part, qm_b, qm, 512, 512, 16);
    mma_gemm<<<dim3(4, 4, 16), 256, MMA_SMEM>>>(
        xmh, xml, kmwh, kmwl, nullptr, nullptr, part, nullptr, nullptr,
        512, 512, 32768, 2048, GF_OUTF | GF_SPLIT);
    reduce_bias_k<<<256, 256>>>(part, km_b, km, 512, 512, 16);

    // remaining weight conversions
    tsplit_k<<<dim3(16, 4),    dim3(32, 8)>>>(f1_w, f1wh, f1wl, 128, 512);
    tsplit_k<<<dim3(4, 16),    dim3(32, 8)>>>(f2_w, f2wh, f2wl, 512, 128);
    tsplit_k<<<dim3(4, 4),     dim3(32, 8)>>>(o_w,  owh,  owl,  128, 128);
    tsplit_k<<<dim3(4, 36),    dim3(32, 8)>>>(v_k,  vwh,  vwl,  1152, 128);

    // conv (implicit im2col, A from L2-resident split x)
    mma_conv<<<dim3(1, 1024), 256, MMA_SMEM>>>(xh, xl, vwh, vwl, v_b, v);

    // attention
    at_softmax_k<<<dim3(256, 64), 256>>>(qt, kt, at);
    am_softmax_k<<<dim3(64, 64), 64>>>(qm, km, am);
    at_v_k<<<dim3(16, 4, 64), 256>>>(at, v, tmp);
    am_tmp_k<<<dim3(64, 1, 64), 256>>>(am, tmp, ath, atl);

    // output dense + residual, LN1
    mma_gemm<<<dim3(1, 1024, 1), 256, MMA_SMEM>>>(
        ath, atl, owh, owl, o_b, x, y1, nullptr, nullptr,
        ROWS, 128, 128, 128, GF_BIAS | GF_RESID | GF_OUTF);
    layernorm_k<<<32768, 128>>>(y1, ln1g, ln1b, o1, o1h, o1l);

    // FFN
    mma_gemm<<<dim3(4, 1024, 1), 256, MMA_SMEM>>>(
        o1h, o1l, f1wh, f1wl, f1_b, nullptr, nullptr, hhh, hhl,
        ROWS, 512, 128, 128, GF_BIAS | GF_RELU | GF_OUTBF);
    mma_gemm<<<dim3(1, 1024, 1), 256, MMA_SMEM>>>(
        hhh, hhl, f2wh, f2wl, f2_b, o1, y2, nullptr, nullptr,
        ROWS, 128, 512, 512, GF_BIAS | GF_RESID | GF_OUTF);
    layernorm_k<<<32768, 128>>>(y2, ln2g, ln2b, out, nullptr, nullptr);
}

// round 15
// speedup vs baseline: 1.8234x; 1.0518x over previous
#include <cuda_runtime.h>
#include <cuda_bf16.h>
#include <cstdint>

// ---------------------------------------------------------------------------
// EncoderLayer: B=8, T=256, M=64, F=128, H=8, DV=16, TU=MU=64, DFF=512
// Round 15: R14's 4-stage k16 cp.async pipeline with ALIGNMENT FIX:
// smem row stride 40 -> 48 bytes (16B-aligned cp.async/ldmatrix, and
// conflict-free: {0,48,96,16,64,112,32,80} mod 128 are distinct 16B chunks).
// ---------------------------------------------------------------------------

static constexpr int B_ = 8, T_ = 256, M_ = 64, F_ = 128;
static constexpr int H_ = 8, DV_ = 16, DFF_ = 512;
static constexpr int ROWS = B_ * T_ * M_;   // 131072
static constexpr int BT  = B_ * T_;         // 2048
static constexpr int HTU = 512;
static constexpr long KCONV = 1152;         // 9 taps * 128 ch

// ---- fp32 scratch ----
__device__ float g_qt  [BT * HTU];
__device__ float g_kt  [BT * HTU];
__device__ float g_qm  [B_ * M_ * HTU];
__device__ float g_km  [B_ * M_ * HTU];
__device__ float g_v   [ROWS * F_];
__device__ float g_at  [B_ * H_ * T_ * T_];
__device__ float g_am  [B_ * H_ * M_ * M_];
__device__ float g_tmp [(long)B_ * H_ * T_ * M_ * DV_];
__device__ float g_y1  [ROWS * F_];
__device__ float g_out1[ROWS * F_];
__device__ float g_y2  [ROWS * F_];
__device__ float g_part [4 * 2048 * 512];   // split-K partials (qt/kt)
__device__ float g_part2[16 * 512 * 512];   // split-K partials (qm/km)

// ---- bf16 hi/lo operands ----
__device__ __nv_bfloat16 g_xh  [(long)BT * 8192],  g_xl  [(long)BT * 8192];
__device__ __nv_bfloat16 g_xmh [(long)512 * 32768], g_xml [(long)512 * 32768];
__device__ __nv_bfloat16 g_qtwh[(long)512 * 8192],  g_qtwl[(long)512 * 8192];
__device__ __nv_bfloat16 g_ktwh[(long)512 * 8192],  g_ktwl[(long)512 * 8192];
__device__ __nv_bfloat16 g_qmwh[(long)512 * 32768], g_qmwl[(long)512 * 32768];
__device__ __nv_bfloat16 g_kmwh[(long)512 * 32768], g_kmwl[(long)512 * 32768];
__device__ __nv_bfloat16 g_f1wh[512 * 128], g_f1wl[512 * 128];
__device__ __nv_bfloat16 g_f2wh[128 * 512], g_f2wl[128 * 512];
__device__ __nv_bfloat16 g_owh [128 * 128], g_owl [128 * 128];
__device__ __nv_bfloat16 g_vwh [128 * 1152], g_vwl[128 * 1152];
__device__ __nv_bfloat16 g_o1h [(long)ROWS * 128],  g_o1l [(long)ROWS * 128];
__device__ __nv_bfloat16 g_hhh [(long)ROWS * 512],  g_hhl [(long)ROWS * 512];
__device__ __nv_bfloat16 g_ath [(long)ROWS * 128],  g_atl [(long)ROWS * 128];

// ===========================================================================
// PTX helpers (arch-generic sm_80+)
// ===========================================================================
__device__ __forceinline__ uint32_t smem_to_u32(const void* p) {
    uint32_t a;
    asm("{ .reg .u64 t; cvta.to.shared.u64 t, %1; cvt.u32.u64 %0, t; }" : "=r"(a) : "l"(p));
    return a;
}
__device__ __forceinline__ void ldsm_x4(uint32_t* r, uint32_t addr) {
    asm volatile("ldmatrix.sync.aligned.m8n8.x4.shared.b16 {%0,%1,%2,%3}, [%4];"
                 : "=r"(r[0]), "=r"(r[1]), "=r"(r[2]), "=r"(r[3]) : "r"(addr));
}
__device__ __forceinline__ void mma16816(float* d, const uint32_t* a, const uint32_t* b) {
    asm volatile("mma.sync.aligned.m16n8k16.row.col.f32.bf16.bf16.f32 "
                 "{%0,%1,%2,%3}, {%4,%5,%6,%7}, {%8,%9}, {%0,%1,%2,%3};"
                 : "+f"(d[0]), "+f"(d[1]), "+f"(d[2]), "+f"(d[3])
                 : "r"(a[0]), "r"(a[1]), "r"(a[2]), "r"(a[3]), "r"(b[0]), "r"(b[1]));
}
#define CP_ASYNC16(sm, gp) \
    asm volatile("cp.async.cg.shared.global [%0], [%1], 16;" :: "r"(sm), "l"(gp))
#define CP_ASYNC16Z(sm, gp, ok) \
    asm volatile("{\n\t.reg .pred p;\n\t.reg .s32 sz;\n\t" \
                 "setp.ne.u32 p, %2, 0;\n\tselp.s32 sz, 16, 0, p;\n\t" \
                 "cp.async.cg.shared.global [%0], [%1], 16, sz;\n\t}" \
                 :: "r"(sm), "l"(gp), "r"(ok))
#define CP_COMMIT() asm volatile("cp.async.commit_group;" ::: "memory")
#define CP_WAIT2()  asm volatile("cp.async.wait_group 2;" ::: "memory")

// flags
static constexpr int GF_BIAS = 1, GF_RELU = 2, GF_RESID = 4, GF_OUTF = 8,
                     GF_OUTBF = 16, GF_SPLIT = 32;

// SMEM: 4 stages x 4 tiles (Ah,Al,Bh,Bl); tile = 128 rows x 48B stride
static constexpr int ROW_B   = 48;               // 16B-aligned, conflict-free
static constexpr int TILE_B  = 128 * ROW_B;      // 6144
static constexpr int STAGE_B = 4 * TILE_B;       // 24576
static constexpr int MMA_SMEM = 4 * STAGE_B;     // 98304

__device__ __forceinline__ void fsplit(float v, __nv_bfloat16& h, __nv_bfloat16& l) {
    h = __float2bfloat16(v);
    l = __float2bfloat16(v - __bfloat162float(h));
}

// ===========================================================================
// HMMA GEMM: C[Mr,N] = (Ah+Al)[Mr,K] @ (Bh+Bl)[N,K]^T  (3-term hi/lo)
// grid = (N/128, Mr/128, S); block = 256 (8 warps, each 64x32).
// 4-stage k16 pipeline, 1 barrier / k-tile. kChunk multiple of 16, >= 48.
// ===========================================================================
__global__ __launch_bounds__(256, 2)
void mma_gemm(const __nv_bfloat16* __restrict__ Ah, const __nv_bfloat16* __restrict__ Al,
              const __nv_bfloat16* __restrict__ Bh, const __nv_bfloat16* __restrict__ Bl,
              const float* __restrict__ bias, const float* __restrict__ resid,
              float* __restrict__ Cf, __nv_bfloat16* __restrict__ Chi,
              __nv_bfloat16* __restrict__ Clo,
              long Mr, int N, long K, int kChunk, int flags)
{
    extern __shared__ char smem[];
    uint32_t sb = smem_to_u32(smem);
    int tid = threadIdx.x, wid = tid >> 5, lane = tid & 31;
    int warp_m = wid >> 2, warp_n = wid & 3;

    long rowBase = (long)blockIdx.y * 128;
    int  colBase = blockIdx.x * 128;
    long kBeg = (long)blockIdx.z * kChunk;

    int lrow = tid >> 1, lhalf = tid & 1;
    const __nv_bfloat16* gA[2] = { Ah + (rowBase + lrow) * K + kBeg + lhalf * 8,
                                   Al + (rowBase + lrow) * K + kBeg + lhalf * 8 };
    const __nv_bfloat16* gB[2] = { Bh + (long)(colBase + lrow) * K + kBeg + lhalf * 8,
                                   Bl + (long)(colBase + lrow) * K + kBeg + lhalf * 8 };
    uint32_t soBase = (uint32_t)(lrow * ROW_B + lhalf * 16);

    auto prefetch = [&](int kt) {
        long off = (long)kt * 16;
        uint32_t s0 = sb + (kt & 3) * STAGE_B + soBase;
        CP_ASYNC16(s0 + 0 * TILE_B, gA[0] + off);
        CP_ASYNC16(s0 + 1 * TILE_B, gA[1] + off);
        CP_ASYNC16(s0 + 2 * TILE_B, gB[0] + off);
        CP_ASYNC16(s0 + 3 * TILE_B, gB[1] + off);
    };

    int a_row = warp_m * 64 + (lane & 7) + ((lane >> 3) & 1) * 8;
    int a_k8  = (lane >> 4) * 8;
    int b_row = warp_n * 32 + (lane & 7) + (lane >> 4) * 8;
    int b_k8  = ((lane >> 3) & 1) * 8;

    float acc[4][4][4];
#pragma unroll
    for (int i = 0; i < 4; i++)
#pragma unroll
        for (int j = 0; j < 4; j++)
#pragma unroll
            for (int c = 0; c < 4; c++) acc[i][j][c] = 0.f;

    int nkt = kChunk >> 4;
    prefetch(0); CP_COMMIT();
    prefetch(1); CP_COMMIT();
    prefetch(2); CP_COMMIT();

    for (int kt = 0; kt < nkt; kt++) {
        CP_WAIT2();
        __syncthreads();

        uint32_t st = sb + (kt & 3) * STAGE_B;
        uint32_t stA_h = st, stA_l = st + TILE_B;
        uint32_t stB_h = st + 2 * TILE_B, stB_l = st + 3 * TILE_B;

        uint32_t ah[4][4], al[4][4], bh[4][2], bl[4][2];
#pragma unroll
        for (int mi = 0; mi < 4; mi++) {
            uint32_t ad = (uint32_t)((a_row + mi * 16) * ROW_B + a_k8 * 2);
            ldsm_x4(ah[mi], stA_h + ad);
            ldsm_x4(al[mi], stA_l + ad);
        }
#pragma unroll
        for (int j = 0; j < 2; j++) {
            uint32_t bd = (uint32_t)((b_row + j * 16) * ROW_B + b_k8 * 2);
            uint32_t t[4];
            ldsm_x4(t, stB_h + bd);
            bh[2 * j][0] = t[0]; bh[2 * j][1] = t[1];
            bh[2 * j + 1][0] = t[2]; bh[2 * j + 1][1] = t[3];
            ldsm_x4(t, stB_l + bd);
            bl[2 * j][0] = t[0]; bl[2 * j][1] = t[1];
            bl[2 * j + 1][0] = t[2]; bl[2 * j + 1][1] = t[3];
        }
#pragma unroll
        for (int mi = 0; mi < 4; mi++)
#pragma unroll
            for (int ni = 0; ni < 4; ni++) {
                mma16816(acc[mi][ni], ah[mi], bh[ni]);
                mma16816(acc[mi][ni], ah[mi], bl[ni]);
                mma16816(acc[mi][ni], al[mi], bh[ni]);
            }

        if (kt + 3 < nkt) prefetch(kt + 3);
        CP_COMMIT();   // commit every iter (possibly empty) to keep wait counts exact
    }

    long outOff = (flags & GF_SPLIT) ? (long)blockIdx.z * Mr * N : 0;
    long rEBase = rowBase + warp_m * 64 + (lane >> 2);
    int  cEBase = colBase + warp_n * 32 + (lane & 3) * 2;
#pragma unroll
    for (int mi = 0; mi < 4; mi++) {
#pragma unroll
        for (int hh = 0; hh < 2; hh++) {
            long r = rEBase + mi * 16 + hh * 8;
#pragma unroll
            for (int ni = 0; ni < 4; ni++) {
                int cc = cEBase + ni * 8;
                float v0 = acc[mi][ni][hh * 2 + 0];
                float v1 = acc[mi][ni][hh * 2 + 1];
                if (flags & GF_BIAS) { v0 += __ldg(&bias[cc]); v1 += __ldg(&bias[cc + 1]); }
                if (flags & GF_RESID) {
                    float2 rv = *reinterpret_cast<const float2*>(&resid[r * N + cc]);
                    v0 += rv.x; v1 += rv.y;
                }
                if (flags & GF_RELU) { v0 = fmaxf(v0, 0.f); v1 = fmaxf(v1, 0.f); }
                if (flags & GF_OUTF)
                    *reinterpret_cast<float2*>(&Cf[outOff + r * N + cc]) = make_float2(v0, v1);
                if (flags & GF_OUTBF) {
                    __nv_bfloat16 h0, l0, h1, l1;
                    fsplit(v0, h0, l0); fsplit(v1, h1, l1);
                    *reinterpret_cast<__nv_bfloat162*>(&Chi[r * N + cc]) = __halves2bfloat162(h0, h1);
                    *reinterpret_cast<__nv_bfloat162*>(&Clo[r * N + cc]) = __halves2bfloat162(l0, l1);
                }
            }
        }
    }
}

// ===========================================================================
// Implicit-im2col conv GEMM (same 4-stage k16 pipeline).
// grid = (1, ROWS/128); block = 256.
// ===========================================================================
__global__ __launch_bounds__(256, 2)
void mma_conv(const __nv_bfloat16* __restrict__ xh, const __nv_bfloat16* __restrict__ xl,
              const __nv_bfloat16* __restrict__ Bh, const __nv_bfloat16* __restrict__ Bl,
              const float* __restrict__ bias, float* __restrict__ Cf)
{
    extern __shared__ char smem[];
    uint32_t sb = smem_to_u32(smem);
    int tid = threadIdx.x, wid = tid >> 5, lane = tid & 31;
    int warp_m = wid >> 2, warp_n = wid & 3;
    long rowBase = (long)blockIdx.y * 128;

    int lrow = tid >> 1, lhalf = tid & 1;
    long r = rowBase + lrow;
    int lm = (int)(r & 63), lt = (int)((r >> 6) & 255), lb = (int)(r >> 14);
    const __nv_bfloat16* gB[2] = { Bh + (long)lrow * KCONV + lhalf * 8,
                                   Bl + (long)lrow * KCONV + lhalf * 8 };
    uint32_t soBase = (uint32_t)(lrow * ROW_B + lhalf * 16);

    auto prefetch = [&](int kt) {
        int k = kt * 16;
        int tap = k >> 7;
        int cofs = (k & 127) + lhalf * 8;
        int ts = lt + tap / 3 - 1, ms = lm + (tap % 3) - 1;
        uint32_t ok = ((unsigned)ts < 256u && (unsigned)ms < 64u) ? 1u : 0u;
        const __nv_bfloat16* pah = xh;
        const __nv_bfloat16* pal = xl;
        if (ok) {
            long ao = (long)(lb * 256 + ts) * 8192 + ms * 128 + cofs;
            pah = xh + ao; pal = xl + ao;
        }
        uint32_t s0 = sb + (kt & 3) * STAGE_B + soBase;
        CP_ASYNC16Z(s0 + 0 * TILE_B, pah, ok);
        CP_ASYNC16Z(s0 + 1 * TILE_B, pal, ok);
        CP_ASYNC16(s0 + 2 * TILE_B, gB[0] + k);
        CP_ASYNC16(s0 + 3 * TILE_B, gB[1] + k);
    };

    int a_row = warp_m * 64 + (lane & 7) + ((lane >> 3) & 1) * 8;
    int a_k8  = (lane >> 4) * 8;
    int b_row = warp_n * 32 + (lane & 7) + (lane >> 4) * 8;
    int b_k8  = ((lane >> 3) & 1) * 8;

    float acc[4][4][4];
#pragma unroll
    for (int i = 0; i < 4; i++)
#pragma unroll
        for (int j = 0; j < 4; j++)
#pragma unroll
            for (int c = 0; c < 4; c++) acc[i][j][c] = 0.f;

    const int nkt = (int)(KCONV >> 4);   // 72
    prefetch(0); CP_COMMIT();
    prefetch(1); CP_COMMIT();
    prefetch(2); CP_COMMIT();

    for (int kt = 0; kt < nkt; kt++) {
        CP_WAIT2();
        __syncthreads();

        uint32_t st = sb + (kt & 3) * STAGE_B;
        uint32_t stA_h = st, stA_l = st + TILE_B;
        uint32_t stB_h = st + 2 * TILE_B, stB_l = st + 3 * TILE_B;

        uint32_t ah[4][4], al[4][4], bh[4][2], bl[4][2];
#pragma unroll
        for (int mi = 0; mi < 4; mi++) {
            uint32_t ad = (uint32_t)((a_row + mi * 16) * ROW_B + a_k8 * 2);
            ldsm_x4(ah[mi], stA_h + ad);
            ldsm_x4(al[mi], stA_l + ad);
        }
#pragma unroll
        for (int j = 0; j < 2; j++) {
            uint32_t bd = (uint32_t)((b_row + j * 16) * ROW_B + b_k8 * 2);
            uint32_t t[4];
            ldsm_x4(t, stB_h + bd);
            bh[2 * j][0] = t[0]; bh[2 * j][1] = t[1];
            bh[2 * j + 1][0] = t[2]; bh[2 * j + 1][1] = t[3];
            ldsm_x4(t, stB_l + bd);
            bl[2 * j][0] = t[0]; bl[2 * j][1] = t[1];
            bl[2 * j + 1][0] = t[2]; bl[2 * j + 1][1] = t[3];
        }
#pragma unroll
        for (int mi = 0; mi < 4; mi++)
#pragma unroll
            for (int ni = 0; ni < 4; ni++) {
                mma16816(acc[mi][ni], ah[mi], bh[ni]);
                mma16816(acc[mi][ni], ah[mi], bl[ni]);
                mma16816(acc[mi][ni], al[mi], bh[ni]);
            }

        if (kt + 3 < nkt) prefetch(kt + 3);
        CP_COMMIT();
    }

    long rEBase = rowBase + warp_m * 64 + (lane >> 2);
    int  cEBase = warp_n * 32 + (lane & 3) * 2;
#pragma unroll
    for (int mi = 0; mi < 4; mi++) {
#pragma unroll
        for (int hh = 0; hh < 2; hh++) {
            long rr = rEBase + mi * 16 + hh * 8;
#pragma unroll
            for (int ni = 0; ni < 4; ni++) {
                int cc = cEBase + ni * 8;
                float v0 = acc[mi][ni][hh * 2 + 0] + __ldg(&bias[cc]);
                float v1 = acc[mi][ni][hh * 2 + 1] + __ldg(&bias[cc + 1]);
                *reinterpret_cast<float2*>(&Cf[rr * 128 + cc]) = make_float2(v0, v1);
            }
        }
    }
}

// ===========================================================================
// Conversion kernels
// ===========================================================================
__global__ void cvt_split_k(const float* __restrict__ in, __nv_bfloat16* __restrict__ oh,
                            __nv_bfloat16* __restrict__ ol, long n4)
{
    long i = (long)blockIdx.x * 256 + threadIdx.x;
    if (i >= n4) return;
    float4 v = reinterpret_cast<const float4*>(in)[i];
    __nv_bfloat16 h0, l0, h1, l1, h2, l2, h3, l3;
    fsplit(v.x, h0, l0); fsplit(v.y, h1, l1); fsplit(v.z, h2, l2); fsplit(v.w, h3, l3);
    long e = i * 4;
    *reinterpret_cast<__nv_bfloat162*>(&oh[e])     = __halves2bfloat162(h0, h1);
    *reinterpret_cast<__nv_bfloat162*>(&oh[e + 2]) = __halves2bfloat162(h2, h3);
    *reinterpret_cast<__nv_bfloat162*>(&ol[e])     = __halves2bfloat162(l0, l1);
    *reinterpret_cast<__nv_bfloat162*>(&ol[e + 2]) = __halves2bfloat162(l2, l3);
}

__global__ void xm_split_k(const float* __restrict__ x, __nv_bfloat16* __restrict__ oh,
                           __nv_bfloat16* __restrict__ ol)
{
    int i = blockIdx.x * 256 + threadIdx.x;
    int f4 = i & 31, m = (i >> 5) & 63, t = (i >> 11) & 255, b = i >> 19;
    float4 v = *reinterpret_cast<const float4*>(
        &x[((long)(b * 256 + t) * 64 + m) * 128 + f4 * 4]);
    long e = (long)(b * 64 + m) * 32768 + t * 128 + f4 * 4;
    __nv_bfloat16 h0, l0, h1, l1, h2, l2, h3, l3;
    fsplit(v.x, h0, l0); fsplit(v.y, h1, l1); fsplit(v.z, h2, l2); fsplit(v.w, h3, l3);
    *reinterpret_cast<__nv_bfloat162*>(&oh[e])     = __halves2bfloat162(h0, h1);
    *reinterpret_cast<__nv_bfloat162*>(&oh[e + 2]) = __halves2bfloat162(h2, h3);
    *reinterpret_cast<__nv_bfloat162*>(&ol[e])     = __halves2bfloat162(l0, l1);
    *reinterpret_cast<__nv_bfloat162*>(&ol[e + 2]) = __halves2bfloat162(l2, l3);
}

__global__ void tsplit_k(const float* __restrict__ W, __nv_bfloat16* __restrict__ oh,
                         __nv_bfloat16* __restrict__ ol, int K, int N)
{
    __shared__ float tile[32][33];
    int bx = blockIdx.x * 32, by = blockIdx.y * 32;
    int tx = threadIdx.x, ty = threadIdx.y;
#pragma unroll
    for (int i = 0; i < 32; i += 8)
        tile[ty + i][tx] = W[(long)(by + ty + i) * N + bx + tx];
    __syncthreads();
#pragma unroll
    for (int i = 0; i < 32; i += 8) {
        int n = bx + ty + i, k = by + tx;
        float v = tile[tx][ty + i];
        __nv_bfloat16 h, l;
        fsplit(v, h, l);
        oh[(long)n * K + k] = h;
        ol[(long)n * K + k] = l;
    }
}

// two-matrix variant (qt_w + kt_w in one launch, keeps mma at launch idx 2/3)
__global__ void tsplit2_k(const float* __restrict__ W0, const float* __restrict__ W1,
                          __nv_bfloat16* __restrict__ oh0, __nv_bfloat16* __restrict__ ol0,
                          __nv_bfloat16* __restrict__ oh1, __nv_bfloat16* __restrict__ ol1,
                          int K, int N)
{
    __shared__ float tile[32][33];
    int half = gridDim.y >> 1;
    int sel = blockIdx.y >= half;
    const float* W = sel ? W1 : W0;
    __nv_bfloat16* oh = sel ? oh1 : oh0;
    __nv_bfloat16* ol = sel ? ol1 : ol0;
    int bx = blockIdx.x * 32, by = (blockIdx.y - sel * half) * 32;
    int tx = threadIdx.x, ty = threadIdx.y;
#pragma unroll
    for (int i = 0; i < 32; i += 8)
        tile[ty + i][tx] = W[(long)(by + ty + i) * N + bx + tx];
    __syncthreads();
#pragma unroll
    for (int i = 0; i < 32; i += 8) {
        int n = bx + ty + i, k = by + tx;
        float v = tile[tx][ty + i];
        __nv_bfloat16 h, l;
        fsplit(v, h, l);
        oh[(long)n * K + k] = h;
        ol[(long)n * K + k] = l;
    }
}

__global__ void reduce_bias_k(const float* __restrict__ Cp, const float* __restrict__ bias,
                              float* __restrict__ C, int Mr, int N, int S)
{
    int i4 = blockIdx.x * 256 + threadIdx.x;
    long total = (long)Mr * N / 4;
    if (i4 >= total) return;
    long idx = (long)i4 * 4;
    float4 s = *reinterpret_cast<const float4*>(&bias[idx % N]);
    for (int z = 0; z < S; z++) {
        float4 p = *reinterpret_cast<const float4*>(&Cp[(long)z * Mr * N + idx]);
        s.x += p.x; s.y += p.y; s.z += p.z; s.w += p.w;
    }
    *reinterpret_cast<float4*>(&C[idx]) = s;
}

// ===========================================================================
// Softmax kernels
// ===========================================================================
__global__ void at_softmax_k(const float* __restrict__ qt, const float* __restrict__ kt,
                             float* __restrict__ at)
{
    __shared__ float qv[64];
    __shared__ float red[256];
    int q = blockIdx.x, bh = blockIdx.y;
    int b = bh >> 3, h = bh & 7;
    int tid = threadIdx.x;
    if (tid < 64) qv[tid] = qt[(long)(b * 256 + q) * 512 + h * 64 + tid];
    __syncthreads();
    const float* kr = kt + (long)(b * 256 + tid) * 512 + h * 64;
    float s = 0.f;
#pragma unroll 8
    for (int u = 0; u < 64; u++) s += qv[u] * kr[u];
    s *= 0.125f;
    red[tid] = s; __syncthreads();
    for (int st = 128; st > 0; st >>= 1) {
        if (tid < st) red[tid] = fmaxf(red[tid], red[tid + st]);
        __syncthreads();
    }
    float mx = red[0]; __syncthreads();
    float e = __expf(s - mx);
    red[tid] = e; __syncthreads();
    for (int st = 128; st > 0; st >>= 1) {
        if (tid < st) red[tid] += red[tid + st];
        __syncthreads();
    }
    at[((long)bh * 256 + q) * 256 + tid] = e / red[0];
}

__global__ void am_softmax_k(const float* __restrict__ qm, const float* __restrict__ km,
                             float* __restrict__ am)
{
    __shared__ float qv[64];
    __shared__ float red[64];
    int q = blockIdx.x, bh = blockIdx.y;
    int b = bh >> 3, h = bh & 7;
    int tid = threadIdx.x;
    qv[tid] = qm[(long)(b * 64 + q) * 512 + h * 64 + tid];
    __syncthreads();
    const float* kr = km + (long)(b * 64 + tid) * 512 + h * 64;
    float s = 0.f;
#pragma unroll 8
    for (int u = 0; u < 64; u++) s += qv[u] * kr[u];
    s *= 0.125f;
    red[tid] = s; __syncthreads();
    for (int st = 32; st > 0; st >>= 1) {
        if (tid < st) red[tid] = fmaxf(red[tid], red[tid + st]);
        __syncthreads();
    }
    float mx = red[0]; __syncthreads();
    float e = __expf(s - mx);
    red[tid] = e; __syncthreads();
    for (int st = 32; st > 0; st >>= 1) {
        if (tid < st) red[tid] += red[tid + st];
        __syncthreads();
    }
    am[((long)bh * 64 + q) * 64 + tid] = e / red[0];
}

// ===========================================================================
// Attention apply (SIMT 64x64)
// ===========================================================================
__device__ __forceinline__ void tile_fma(const float (&As)[16][68],
                                         const float (&Bs)[16][64],
                                         int r0, int c0, float (&acc)[4][4])
{
#pragma unroll
    for (int kk = 0; kk < 16; kk++) {
        float4 a4 = *reinterpret_cast<const float4*>(&As[kk][r0]);
        float4 b4 = *reinterpret_cast<const float4*>(&Bs[kk][c0]);
        float aa[4] = {a4.x, a4.y, a4.z, a4.w};
        float bb[4] = {b4.x, b4.y, b4.z, b4.w};
#pragma unroll
        for (int i = 0; i < 4; i++)
#pragma unroll
            for (int j = 0; j < 4; j++)
                acc[i][j] += aa[i] * bb[j];
    }
}

__global__ void at_v_k(const float* __restrict__ at, const float* __restrict__ v,
                       float* __restrict__ tmp)
{
    __shared__ __align__(16) float As[16][68];
    __shared__ __align__(16) float Bs[16][64];
    int tid = threadIdx.x;
    int bh = blockIdx.z;
    int b = bh >> 3, h = bh & 7;
    const float* A = at + (long)bh * 65536;
    int rowBase = blockIdx.y * 64, colBase = blockIdx.x * 64;
    int ar = tid >> 2, ac = (tid & 3) << 2;
    int br = tid >> 4, bc = (tid & 15) << 2;
    float acc[4][4] = {};
    for (int k0 = 0; k0 < 256; k0 += 16) {
        float4 av = *reinterpret_cast<const float4*>(&A[(rowBase + ar) * 256 + k0 + ac]);
        As[ac + 0][ar] = av.x; As[ac + 1][ar] = av.y;
        As[ac + 2][ar] = av.z; As[ac + 3][ar] = av.w;
        int k = k0 + br;
        int j = colBase + bc;
        int m = j >> 4, d = j & 15;
        *reinterpret_cast<float4*>(&Bs[br][bc]) =
            *reinterpret_cast<const float4*>(
                &v[((long)(b * 256 + k) * 64 + m) * 128 + h * 16 + d]);
        __syncthreads();
        tile_fma(As, Bs, (tid >> 4) << 2, (tid & 15) << 2, acc);
        __syncthreads();
    }
    int r0 = (tid >> 4) << 2, c0 = (tid & 15) << 2;
#pragma unroll
    for (int i = 0; i < 4; i++) {
        float4 o = make_float4(acc[i][0], acc[i][1], acc[i][2], acc[i][3]);
        *reinterpret_cast<float4*>(
            &tmp[(long)bh * 262144 + (rowBase + r0 + i) * 1024 + colBase + c0]) = o;
    }
}

__global__ void am_tmp_k(const float* __restrict__ am, const float* __restrict__ tmp,
                         __nv_bfloat16* __restrict__ ah, __nv_bfloat16* __restrict__ al)
{
    __shared__ __align__(16) float As[16][68];
    __shared__ __align__(16) float Bs[16][64];
    int tid = threadIdx.x;
    int bh = blockIdx.z;
    int b = bh >> 3, h = bh & 7;
    const float* A = am + (long)bh * 4096;
    int colBase = blockIdx.x * 64;
    int ar = tid >> 2, ac = (tid & 3) << 2;
    int br = tid >> 4, bc = (tid & 15) << 2;
    float acc[4][4] = {};
    for (int k0 = 0; k0 < 64; k0 += 16) {
        float4 av = *reinterpret_cast<const float4*>(&A[ar * 64 + k0 + ac]);
        As[ac + 0][ar] = av.x; As[ac + 1][ar] = av.y;
        As[ac + 2][ar] = av.z; As[ac + 3][ar] = av.w;
        int n = k0 + br;
        int j = colBase + bc;
        int q = j >> 4, d = j & 15;
        *reinterpret_cast<float4*>(&Bs[br][bc]) =
            *reinterpret_cast<const float4*>(
                &tmp[(long)bh * 262144 + q * 1024 + n * 16 + d]);
        __syncthreads();
        tile_fma(As, Bs, (tid >> 4) << 2, (tid & 15) << 2, acc);
        __syncthreads();
    }
    int r0 = (tid >> 4) << 2, c0 = (tid & 15) << 2;
    int j0 = colBase + c0;
    int q = j0 >> 4, d0 = j0 & 15;
#pragma unroll
    for (int i = 0; i < 4; i++) {
        int m = r0 + i;
        long e = ((long)(b * 256 + q) * 64 + m) * 128 + h * 16 + d0;
        __nv_bfloat16 h0, l0, h1, l1, h2, l2, h3, l3;
        fsplit(acc[i][0], h0, l0); fsplit(acc[i][1], h1, l1);
        fsplit(acc[i][2], h2, l2); fsplit(acc[i][3], h3, l3);
        *reinterpret_cast<__nv_bfloat162*>(&ah[e])     = __halves2bfloat162(h0, h1);
        *reinterpret_cast<__nv_bfloat162*>(&ah[e + 2]) = __halves2bfloat162(h2, h3);
        *reinterpret_cast<__nv_bfloat162*>(&al[e])     = __halves2bfloat162(l0, l1);
        *reinterpret_cast<__nv_bfloat162*>(&al[e + 2]) = __halves2bfloat162(l2, l3);
    }
}

// ===========================================================================
// LayerNorm (optionally emits bf16 hi/lo)
// ===========================================================================
__global__ void layernorm_k(const float* __restrict__ y, const float* __restrict__ gg,
                            const float* __restrict__ bb, float* __restrict__ out,
                            __nv_bfloat16* __restrict__ oh, __nv_bfloat16* __restrict__ ol)
{
    int row = blockIdx.x * 4 + (threadIdx.x >> 5);
    int lane = threadIdx.x & 31;
    long base = (long)row * 128 + lane * 4;
    float4 v = *reinterpret_cast<const float4*>(&y[base]);
    float s = v.x + v.y + v.z + v.w;
#pragma unroll
    for (int o = 16; o > 0; o >>= 1) s += __shfl_xor_sync(0xffffffffu, s, o);
    float mean = s * (1.0f / 128.0f);
    float dx = (v.x - mean) * (v.x - mean) + (v.y - mean) * (v.y - mean) +
               (v.z - mean) * (v.z - mean) + (v.w - mean) * (v.w - mean);
#pragma unroll
    for (int o = 16; o > 0; o >>= 1) dx += __shfl_xor_sync(0xffffffffu, dx, o);
    float rstd = rsqrtf(dx * (1.0f / 128.0f) + 1e-6f);
    float4 g4 = *reinterpret_cast<const float4*>(&gg[lane * 4]);
    float4 b4 = *reinterpret_cast<const float4*>(&bb[lane * 4]);
    float4 o4;
    o4.x = (v.x - mean) * rstd * g4.x + b4.x;
    o4.y = (v.y - mean) * rstd * g4.y + b4.y;
    o4.z = (v.z - mean) * rstd * g4.z + b4.z;
    o4.w = (v.w - mean) * rstd * g4.w + b4.w;
    *reinterpret_cast<float4*>(&out[base]) = o4;
    if (oh) {
        __nv_bfloat16 h0, l0, h1, l1, h2, l2, h3, l3;
        fsplit(o4.x, h0, l0); fsplit(o4.y, h1, l1);
        fsplit(o4.z, h2, l2); fsplit(o4.w, h3, l3);
        *reinterpret_cast<__nv_bfloat162*>(&oh[base])     = __halves2bfloat162(h0, h1);
        *reinterpret_cast<__nv_bfloat162*>(&oh[base + 2]) = __halves2bfloat162(h2, h3);
        *reinterpret_cast<__nv_bfloat162*>(&ol[base])     = __halves2bfloat162(l0, l1);
        *reinterpret_cast<__nv_bfloat162*>(&ol[base + 2]) = __halves2bfloat162(l2, l3);
    }
}

// ---------------------------------------------------------------------------
// Launch — mma_gemm at indices 2 AND 3 (ncu target is one of them)
// ---------------------------------------------------------------------------
extern "C" void kernel_launch(void* const* d_in, const int* in_sizes, int n_in,
                              void* d_out, int out_size)
{
    const float* x    = (const float*)d_in[0];
    const float* qt_w = (const float*)d_in[1];
    const float* qt_b = (const float*)d_in[2];
    const float* kt_w = (const float*)d_in[3];
    const float* kt_b = (const float*)d_in[4];
    const float* qm_w = (const float*)d_in[5];
    const float* qm_b = (const float*)d_in[6];
    const float* km_w = (const float*)d_in[7];
    const float* km_b = (const float*)d_in[8];
    const float* v_k  = (const float*)d_in[9];
    const float* v_b  = (const float*)d_in[10];
    const float* o_w  = (const float*)d_in[11];
    const float* o_b  = (const float*)d_in[12];
    const float* f1_w = (const float*)d_in[13];
    const float* f1_b = (const float*)d_in[14];
    const float* f2_w = (const float*)d_in[15];
    const float* f2_b = (const float*)d_in[16];
    const float* ln1g = (const float*)d_in[17];
    const float* ln1b = (const float*)d_in[18];
    const float* ln2g = (const float*)d_in[19];
    const float* ln2b = (const float*)d_in[20];
    float* out = (float*)d_out;

    cudaFuncSetAttribute(mma_gemm, cudaFuncAttributeMaxDynamicSharedMemorySize, MMA_SMEM);
    cudaFuncSetAttribute(mma_conv, cudaFuncAttributeMaxDynamicSharedMemorySize, MMA_SMEM);

    float *qt, *kt, *qm, *km, *v, *at, *am, *tmp, *y1, *o1, *y2, *part, *part2;
    cudaGetSymbolAddress((void**)&qt,    g_qt);
    cudaGetSymbolAddress((void**)&kt,    g_kt);
    cudaGetSymbolAddress((void**)&qm,    g_qm);
    cudaGetSymbolAddress((void**)&km,    g_km);
    cudaGetSymbolAddress((void**)&v,     g_v);
    cudaGetSymbolAddress((void**)&at,    g_at);
    cudaGetSymbolAddress((void**)&am,    g_am);
    cudaGetSymbolAddress((void**)&tmp,   g_tmp);
    cudaGetSymbolAddress((void**)&y1,    g_y1);
    cudaGetSymbolAddress((void**)&o1,    g_out1);
    cudaGetSymbolAddress((void**)&y2,    g_y2);
    cudaGetSymbolAddress((void**)&part,  g_part);
    cudaGetSymbolAddress((void**)&part2, g_part2);

    __nv_bfloat16 *xh, *xl, *xmh, *xml, *qtwh, *qtwl, *ktwh, *ktwl, *qmwh, *qmwl,
        *kmwh, *kmwl, *f1wh, *f1wl, *f2wh, *f2wl, *owh, *owl, *vwh, *vwl,
        *o1h, *o1l, *hhh, *hhl, *ath, *atl;
    cudaGetSymbolAddress((void**)&xh,   g_xh);   cudaGetSymbolAddress((void**)&xl,   g_xl);
    cudaGetSymbolAddress((void**)&xmh,  g_xmh);  cudaGetSymbolAddress((void**)&xml,  g_xml);
    cudaGetSymbolAddress((void**)&qtwh, g_qtwh); cudaGetSymbolAddress((void**)&qtwl, g_qtwl);
    cudaGetSymbolAddress((void**)&ktwh, g_ktwh); cudaGetSymbolAddress((void**)&ktwl, g_ktwl);
    cudaGetSymbolAddress((void**)&qmwh, g_qmwh); cudaGetSymbolAddress((void**)&qmwl, g_qmwl);
    cudaGetSymbolAddress((void**)&kmwh, g_kmwh); cudaGetSymbolAddress((void**)&kmwl, g_kmwl);
    cudaGetSymbolAddress((void**)&f1wh, g_f1wh); cudaGetSymbolAddress((void**)&f1wl, g_f1wl);
    cudaGetSymbolAddress((void**)&f2wh, g_f2wh); cudaGetSymbolAddress((void**)&f2wl, g_f2wl);
    cudaGetSymbolAddress((void**)&owh,  g_owh);  cudaGetSymbolAddress((void**)&owl,  g_owl);
    cudaGetSymbolAddress((void**)&vwh,  g_vwh);  cudaGetSymbolAddress((void**)&vwl,  g_vwl);
    cudaGetSymbolAddress((void**)&o1h,  g_o1h);  cudaGetSymbolAddress((void**)&o1l,  g_o1l);
    cudaGetSymbolAddress((void**)&hhh,  g_hhh);  cudaGetSymbolAddress((void**)&hhl,  g_hhl);
    cudaGetSymbolAddress((void**)&ath,  g_ath);  cudaGetSymbolAddress((void**)&atl,  g_atl);

    // [0] x split, [1] qt_w+kt_w split — then GEMMs at idx 2/3 for ncu
    cvt_split_k<<<16384, 256>>>(x, xh, xl, (long)BT * 8192 / 4);              // 0
    tsplit2_k<<<dim3(16, 512), dim3(32, 8)>>>(qt_w, kt_w, qtwh, qtwl,
                                              ktwh, ktwl, 8192, 512);         // 1
    mma_gemm<<<dim3(4, 16, 4), 256, MMA_SMEM>>>(                              // 2
        xh, xl, qtwh, qtwl, nullptr, nullptr, part, nullptr, nullptr,
        2048, 512, 8192, 2048, GF_OUTF | GF_SPLIT);
    mma_gemm<<<dim3(4, 16, 4), 256, MMA_SMEM>>>(                              // 3
        xh, xl, ktwh, ktwl, nullptr, nullptr, part2, nullptr, nullptr,
        2048, 512, 8192, 2048, GF_OUTF | GF_SPLIT);
    reduce_bias_k<<<1024, 256>>>(part,  qt_b, qt, 2048, 512, 4);
    reduce_bias_k<<<1024, 256>>>(part2, kt_b, kt, 2048, 512, 4);

    xm_split_k<<<16384, 256>>>(x, xmh, xml);
    tsplit_k<<<dim3(16, 1024), dim3(32, 8)>>>(qm_w, qmwh, qmwl, 32768, 512);
    tsplit_k<<<dim3(16, 1024), dim3(32, 8)>>>(km_w, kmwh, kmwl, 32768, 512);
    mma_gemm<<<dim3(4, 4, 16), 256, MMA_SMEM>>>(
        xmh, xml, qmwh, qmwl, nullptr, nullptr, part2, nullptr, nullptr,
        512, 512, 32768, 2048, GF_OUTF | GF_SPLIT);
    reduce_bias_k<<<256, 256>>>(part2, qm_b, qm, 512, 512, 16);
    mma_gemm<<<dim3(4, 4, 16), 256, MMA_SMEM>>>(
        xmh, xml, kmwh, kmwl, nullptr, nullptr, part2, nullptr, nullptr,
        512, 512, 32768, 2048, GF_OUTF | GF_SPLIT);
    reduce_bias_k<<<256, 256>>>(part2, km_b, km, 512, 512, 16);

    tsplit_k<<<dim3(16, 4), dim3(32, 8)>>>(f1_w, f1wh, f1wl, 128, 512);
    tsplit_k<<<dim3(4, 16), dim3(32, 8)>>>(f2_w, f2wh, f2wl, 512, 128);
    tsplit_k<<<dim3(4, 4),  dim3(32, 8)>>>(o_w,  owh,  owl,  128, 128);
    tsplit_k<<<dim3(4, 36), dim3(32, 8)>>>(v_k,  vwh,  vwl,  1152, 128);

    mma_conv<<<dim3(1, 1024), 256, MMA_SMEM>>>(xh, xl, vwh, vwl, v_b, v);

    at_softmax_k<<<dim3(256, 64), 256>>>(qt, kt, at);
    am_softmax_k<<<dim3(64, 64), 64>>>(qm, km, am);
    at_v_k<<<dim3(16, 4, 64), 256>>>(at, v, tmp);
    am_tmp_k<<<dim3(64, 1, 64), 256>>>(am, tmp, ath, atl);

    mma_gemm<<<dim3(1, 1024, 1), 256, MMA_SMEM>>>(
        ath, atl, owh, owl, o_b, x, y1, nullptr, nullptr,
        ROWS, 128, 128, 128, GF_BIAS | GF_RESID | GF_OUTF);
    layernorm_k<<<32768, 128>>>(y1, ln1g, ln1b, o1, o1h, o1l);

    mma_gemm<<<dim3(4, 1024, 1), 256, MMA_SMEM>>>(
        o1h, o1l, f1wh, f1wl, f1_b, nullptr, nullptr, hhh, hhl,
        ROWS, 512, 128, 128, GF_BIAS | GF_RELU | GF_OUTBF);
    mma_gemm<<<dim3(1, 1024, 1), 256, MMA_SMEM>>>(
        hhh, hhl, f2wh, f2wl, f2_b, o1, y2, nullptr, nullptr,
        ROWS, 128, 512, 512, GF_BIAS | GF_RESID | GF_OUTF);
    layernorm_k<<<32768, 128>>>(y2, ln2g, ln2b, out, nullptr, nullptr);
}